// round 1
// baseline (speedup 1.0000x reference)
#include <cuda_runtime.h>
#include <math.h>

// ---------------- problem constants ----------------
#define BATCH   2
#define LSEQ    1024
#define DMODEL  1024
#define DINNER  2048
#define DSTATE  16
#define DTRANK  64
#define KCONV   4
#define TOK     (BATCH*LSEQ)        // 2048 tokens
#define XDBL_N  (DTRANK + 2*DSTATE) // 96
#define EPS     1e-5f

// ---------------- scratch (no cudaMalloc allowed) ----------------
__device__ float g_h    [TOK * DMODEL];      // rmsnorm output          8 MB
__device__ float g_xres [TOK * 2 * DINNER];  // in_proj out (x|res)    32 MB
__device__ float g_xc   [TOK * DINNER];      // conv+silu output       16 MB
__device__ float g_xdbl [TOK * XDBL_N];      // x_proj out             0.75 MB
__device__ float g_delta[TOK * DINNER];      // softplus(dt)           16 MB
__device__ float g_y    [TOK * DINNER];      // scan output (gated)    16 MB

// ---------------- RMSNorm ----------------
__global__ void rmsnorm_kernel(const float* __restrict__ x0,
                               const float* __restrict__ w) {
    int t = blockIdx.x;                 // token
    const float* xr = x0 + (size_t)t * DMODEL;
    float s = 0.f;
    #pragma unroll
    for (int i = 0; i < DMODEL / 256; i++) {
        float v = xr[threadIdx.x + i * 256];
        s += v * v;
    }
    // warp reduce
    #pragma unroll
    for (int o = 16; o > 0; o >>= 1) s += __shfl_xor_sync(0xffffffffu, s, o);
    __shared__ float ws[8];
    if ((threadIdx.x & 31) == 0) ws[threadIdx.x >> 5] = s;
    __syncthreads();
    if (threadIdx.x < 8) {
        float v = ws[threadIdx.x];
        #pragma unroll
        for (int o = 4; o > 0; o >>= 1) v += __shfl_xor_sync(0xffu, v, o);
        if (threadIdx.x == 0) ws[0] = v;
    }
    __syncthreads();
    float rs = rsqrtf(ws[0] / (float)DMODEL + EPS);
    float* hr = g_h + (size_t)t * DMODEL;
    #pragma unroll
    for (int i = 0; i < DMODEL / 256; i++) {
        int c = threadIdx.x + i * 256;
        hr[c] = xr[c] * rs * w[c];
    }
}

// ---------------- SGEMM: C[M,N] = A[M,K] @ B[K,N] (+ residual) ----------------
// 128x128 tile, BK=16, 256 threads, 8x8 per thread.
#define BM 128
#define BN 128
#define BK 16

__global__ void sgemm_kernel(const float* __restrict__ A,
                             const float* __restrict__ B,
                             float* __restrict__ C,
                             int M, int N, int Kd,
                             const float* __restrict__ residual) {
    __shared__ float As[BK][BM];
    __shared__ float Bs[BK][BN];

    int tid = threadIdx.x;
    int bm = blockIdx.y * BM;
    int bn = blockIdx.x * BN;
    int tx = tid & 15;        // 0..15  (N dir)
    int ty = tid >> 4;        // 0..15  (M dir)

    float acc[8][8];
    #pragma unroll
    for (int i = 0; i < 8; i++)
        #pragma unroll
        for (int j = 0; j < 8; j++) acc[i][j] = 0.f;

    // A loader: row = tid>>1 (0..127), col = (tid&1)*8
    int arow = tid >> 1;
    int acol = (tid & 1) * 8;
    // B loader: row = tid>>4 (0..15), col = (tid&15)*8
    int brow = tid >> 4;
    int bcol = (tid & 15) * 8;

    for (int k0 = 0; k0 < Kd; k0 += BK) {
        // ---- load A tile (M,K exact multiples of tile here) ----
        {
            const float* src = A + (size_t)(bm + arow) * Kd + k0 + acol;
            float4 v0 = *reinterpret_cast<const float4*>(src);
            float4 v1 = *reinterpret_cast<const float4*>(src + 4);
            As[acol + 0][arow] = v0.x; As[acol + 1][arow] = v0.y;
            As[acol + 2][arow] = v0.z; As[acol + 3][arow] = v0.w;
            As[acol + 4][arow] = v1.x; As[acol + 5][arow] = v1.y;
            As[acol + 6][arow] = v1.z; As[acol + 7][arow] = v1.w;
        }
        // ---- load B tile (guard N for ragged case N=96) ----
        {
            const float* src = B + (size_t)(k0 + brow) * N + bn + bcol;
            if (bn + bcol + 8 <= N) {
                float4 v0 = *reinterpret_cast<const float4*>(src);
                float4 v1 = *reinterpret_cast<const float4*>(src + 4);
                Bs[brow][bcol + 0] = v0.x; Bs[brow][bcol + 1] = v0.y;
                Bs[brow][bcol + 2] = v0.z; Bs[brow][bcol + 3] = v0.w;
                Bs[brow][bcol + 4] = v1.x; Bs[brow][bcol + 5] = v1.y;
                Bs[brow][bcol + 6] = v1.z; Bs[brow][bcol + 7] = v1.w;
            } else {
                #pragma unroll
                for (int j = 0; j < 8; j++)
                    Bs[brow][bcol + j] = (bn + bcol + j < N) ? src[j] : 0.f;
            }
        }
        __syncthreads();

        #pragma unroll
        for (int k = 0; k < BK; k++) {
            float a[8], b[8];
            #pragma unroll
            for (int i = 0; i < 8; i++) a[i] = As[k][ty * 8 + i];
            #pragma unroll
            for (int j = 0; j < 8; j++) b[j] = Bs[k][tx * 8 + j];
            #pragma unroll
            for (int i = 0; i < 8; i++)
                #pragma unroll
                for (int j = 0; j < 8; j++)
                    acc[i][j] = fmaf(a[i], b[j], acc[i][j]);
        }
        __syncthreads();
    }

    // ---- store ----
    #pragma unroll
    for (int i = 0; i < 8; i++) {
        int r = bm + ty * 8 + i;
        float* crow = C + (size_t)r * N;
        const float* rrow = residual ? residual + (size_t)r * N : nullptr;
        #pragma unroll
        for (int j = 0; j < 8; j++) {
            int c = bn + tx * 8 + j;
            if (c < N) {
                float v = acc[i][j];
                if (rrow) v += rrow[c];
                crow[c] = v;
            }
        }
    }
}

// ---------------- causal depthwise conv (K=4) + SiLU ----------------
__global__ void conv_silu_kernel(const float* __restrict__ conv_w,
                                 const float* __restrict__ conv_b) {
    int idx = blockIdx.x * blockDim.x + threadIdx.x; // t*DINNER + d
    if (idx >= TOK * DINNER) return;
    int d = idx & (DINNER - 1);
    int t = idx >> 11;          // /2048
    int b = t >> 10;            // /1024
    int l = t & (LSEQ - 1);

    float w0 = conv_w[d * KCONV + 0];
    float w1 = conv_w[d * KCONV + 1];
    float w2 = conv_w[d * KCONV + 2];
    float w3 = conv_w[d * KCONV + 3];
    float acc = conv_b[d];

    const float* base = g_xres + ((size_t)b * LSEQ) * (2 * DINNER) + d;
    // x lives in first DINNER columns of g_xres, row stride 2*DINNER
    if (l - 3 >= 0) acc = fmaf(base[(size_t)(l - 3) * (2 * DINNER)], w0, acc);
    if (l - 2 >= 0) acc = fmaf(base[(size_t)(l - 2) * (2 * DINNER)], w1, acc);
    if (l - 1 >= 0) acc = fmaf(base[(size_t)(l - 1) * (2 * DINNER)], w2, acc);
    acc = fmaf(base[(size_t)l * (2 * DINNER)], w3, acc);

    float sil = acc / (1.f + __expf(-acc));
    g_xc[idx] = sil;
}

// ---------------- delta = softplus(dlt @ W_dt + b_dt) ----------------
__global__ void delta_kernel(const float* __restrict__ W_dt,
                             const float* __restrict__ b_dt) {
    int t = blockIdx.x;  // token
    __shared__ float s_dlt[DTRANK];
    if (threadIdx.x < DTRANK)
        s_dlt[threadIdx.x] = g_xdbl[(size_t)t * XDBL_N + threadIdx.x];
    __syncthreads();

    #pragma unroll
    for (int rep = 0; rep < DINNER / 256; rep++) {
        int col = threadIdx.x + rep * 256;
        float acc = b_dt[col];
        #pragma unroll 8
        for (int k = 0; k < DTRANK; k++)
            acc = fmaf(s_dlt[k], W_dt[(size_t)k * DINNER + col], acc);
        // softplus
        float sp = (acc > 20.f) ? acc : log1pf(__expf(acc));
        g_delta[(size_t)t * DINNER + col] = sp;
    }
}

// ---------------- selective scan (+ D skip, + silu(res) gate) ----------------
// one thread per (b, d) channel, 16 states in registers.
__global__ void scan_kernel(const float* __restrict__ A,
                            const float* __restrict__ Dp) {
    int g = blockIdx.x * blockDim.x + threadIdx.x;
    if (g >= BATCH * DINNER) return;
    int b = g / DINNER;
    int d = g % DINNER;

    float a[DSTATE], s[DSTATE];
    #pragma unroll
    for (int n = 0; n < DSTATE; n++) { a[n] = A[d * DSTATE + n]; s[n] = 0.f; }
    float Dd = Dp[d];

    for (int l = 0; l < LSEQ; l++) {
        int t = b * LSEQ + l;
        float delta = g_delta[(size_t)t * DINNER + d];
        float xv    = g_xc   [(size_t)t * DINNER + d];
        float du    = delta * xv;
        const float* bc = g_xdbl + (size_t)t * XDBL_N;
        float yacc = 0.f;
        #pragma unroll
        for (int n = 0; n < DSTATE; n++) {
            float dA = __expf(delta * a[n]);
            float Bn = bc[DTRANK + n];
            float Cn = bc[DTRANK + DSTATE + n];
            s[n] = fmaf(dA, s[n], du * Bn);
            yacc = fmaf(s[n], Cn, yacc);
        }
        float res = g_xres[(size_t)t * (2 * DINNER) + DINNER + d];
        float gate = res / (1.f + __expf(-res));
        g_y[(size_t)t * DINNER + d] = (yacc + xv * Dd) * gate;
    }
}

// ---------------- launch ----------------
extern "C" void kernel_launch(void* const* d_in, const int* in_sizes, int n_in,
                              void* d_out, int out_size) {
    const float* x0     = (const float*)d_in[0];   // [2,1024,1024]
    const float* norm_w = (const float*)d_in[1];   // [1024]
    const float* W_in   = (const float*)d_in[2];   // [1024,4096]
    const float* conv_w = (const float*)d_in[3];   // [2048,4]
    const float* conv_b = (const float*)d_in[4];   // [2048]
    const float* W_x    = (const float*)d_in[5];   // [2048,96]
    const float* W_dt   = (const float*)d_in[6];   // [64,2048]
    const float* b_dt   = (const float*)d_in[7];   // [2048]
    const float* Amat   = (const float*)d_in[8];   // [2048,16]
    const float* Dvec   = (const float*)d_in[9];   // [2048]
    const float* W_out  = (const float*)d_in[10];  // [2048,1024]
    float* out = (float*)d_out;                    // [2,1024,1024]

    float *p_h, *p_xres, *p_xc, *p_xdbl, *p_delta, *p_y;
    cudaGetSymbolAddress((void**)&p_h,     g_h);
    cudaGetSymbolAddress((void**)&p_xres,  g_xres);
    cudaGetSymbolAddress((void**)&p_xc,    g_xc);
    cudaGetSymbolAddress((void**)&p_xdbl,  g_xdbl);
    cudaGetSymbolAddress((void**)&p_delta, g_delta);
    cudaGetSymbolAddress((void**)&p_y,     g_y);

    // 1) RMSNorm
    rmsnorm_kernel<<<TOK, 256>>>(x0, norm_w);

    // 2) in_proj: h[2048,1024] @ W_in[1024,4096] -> g_xres
    sgemm_kernel<<<dim3(4096 / BN, TOK / BM), 256>>>(
        p_h, W_in, p_xres, TOK, 2 * DINNER, DMODEL, nullptr);

    // 3) conv + silu -> g_xc
    conv_silu_kernel<<<(TOK * DINNER + 255) / 256, 256>>>(conv_w, conv_b);

    // 4) x_proj: g_xc[2048,2048] @ W_x[2048,96] -> g_xdbl
    sgemm_kernel<<<dim3(1, TOK / BM), 256>>>(
        p_xc, W_x, p_xdbl, TOK, XDBL_N, DINNER, nullptr);

    // 5) delta
    delta_kernel<<<TOK, 256>>>(W_dt, b_dt);

    // 6) scan + gate -> g_y
    scan_kernel<<<(BATCH * DINNER) / 256, 256>>>(Amat, Dvec);

    // 7) out_proj with residual: out = x0 + g_y @ W_out
    sgemm_kernel<<<dim3(DMODEL / BN, TOK / BM), 256>>>(
        p_y, W_out, out, TOK, DMODEL, DINNER, x0);
}

// round 2
// speedup vs baseline: 4.8146x; 4.8146x over previous
#include <cuda_runtime.h>
#include <math.h>
#include <stdint.h>

// ---------------- problem constants ----------------
#define BATCH   2
#define LSEQ    1024
#define DMODEL  1024
#define DINNER  2048
#define DSTATE  16
#define DTRANK  64
#define KCONV   4
#define TOK     (BATCH*LSEQ)        // 2048 tokens
#define XDBL_N  (DTRANK + 2*DSTATE) // 96
#define EPS     1e-5f

#define NCHUNK  32
#define CLEN    (LSEQ/NCHUNK)       // 32
#define DN      (DINNER*DSTATE)     // 32768

// ---------------- scratch (no cudaMalloc allowed) ----------------
__device__ float g_h    [TOK * DMODEL];
__device__ float g_xres [TOK * 2 * DINNER];
__device__ float g_xc   [TOK * DINNER];
__device__ float g_xdbl [TOK * XDBL_N];
__device__ float g_delta[TOK * DINNER];
__device__ float g_y    [TOK * DINNER];
__device__ float g_xp   [4 * TOK * XDBL_N];          // split-K partials
__device__ float g_S    [BATCH * NCHUNK * DN];       // chunk-local final states
__device__ float g_P    [BATCH * NCHUNK * DN];       // chunk dA products
__device__ float g_SI   [BATCH * NCHUNK * DN];       // chunk initial states

// ---------------- helpers ----------------
__device__ __forceinline__ uint32_t f2tf(float f) {
    uint32_t r;
    asm("cvt.rna.tf32.f32 %0, %1;" : "=r"(r) : "f"(f));
    return r;
}
__device__ __forceinline__ void mma_tf32(float c[4],
    uint32_t a0, uint32_t a1, uint32_t a2, uint32_t a3,
    uint32_t b0, uint32_t b1) {
    asm volatile(
        "mma.sync.aligned.m16n8k8.row.col.f32.tf32.tf32.f32 "
        "{%0,%1,%2,%3}, {%4,%5,%6,%7}, {%8,%9}, {%0,%1,%2,%3};"
        : "+f"(c[0]), "+f"(c[1]), "+f"(c[2]), "+f"(c[3])
        : "r"(a0), "r"(a1), "r"(a2), "r"(a3), "r"(b0), "r"(b1));
}
__device__ __forceinline__ float silu_f(float x) {
    return x / (1.f + __expf(-x));
}

// ---------------- RMSNorm ----------------
__global__ void rmsnorm_kernel(const float* __restrict__ x0,
                               const float* __restrict__ w) {
    int t = blockIdx.x;
    const float* xr = x0 + (size_t)t * DMODEL;
    float s = 0.f;
    #pragma unroll
    for (int i = 0; i < DMODEL / 256; i++) {
        float v = xr[threadIdx.x + i * 256];
        s += v * v;
    }
    #pragma unroll
    for (int o = 16; o > 0; o >>= 1) s += __shfl_xor_sync(0xffffffffu, s, o);
    __shared__ float ws[8];
    if ((threadIdx.x & 31) == 0) ws[threadIdx.x >> 5] = s;
    __syncthreads();
    if (threadIdx.x < 8) {
        float v = ws[threadIdx.x];
        #pragma unroll
        for (int o = 4; o > 0; o >>= 1) v += __shfl_xor_sync(0xffu, v, o);
        if (threadIdx.x == 0) ws[0] = v;
    }
    __syncthreads();
    float rs = rsqrtf(ws[0] / (float)DMODEL + EPS);
    float* hr = g_h + (size_t)t * DMODEL;
    #pragma unroll
    for (int i = 0; i < DMODEL / 256; i++) {
        int c = threadIdx.x + i * 256;
        hr[c] = xr[c] * rs * w[c];
    }
}

// ---------------- TF32 MMA GEMM: C[M,N] = A[M,K] @ B[K,N] (+residual) ------
// 128x128 tile, BK=16, 256 threads (8 warps, 2x4), warp tile 64x32 via m16n8k8.
// Requires M%128==0, N%128==0, K%16==0.
__global__ void __launch_bounds__(256)
mma_gemm(const float* __restrict__ A, const float* __restrict__ B,
         float* __restrict__ C, int M, int N, int K,
         const float* __restrict__ residual) {
    __shared__ uint32_t As[2][16][136];  // [k][m], padded (8tig+gid distinct banks)
    __shared__ uint32_t Bs[2][16][136];  // [k][n]

    int tid  = threadIdx.x;
    int lane = tid & 31, wid = tid >> 5;
    int bm = blockIdx.y * 128, bn = blockIdx.x * 128;
    int wm = (wid >> 2) * 64, wn = (wid & 3) * 32;
    int gid = lane >> 2, tig = lane & 3;

    float acc[4][4][4];
    #pragma unroll
    for (int i = 0; i < 4; i++)
        #pragma unroll
        for (int j = 0; j < 4; j++)
            #pragma unroll
            for (int q = 0; q < 4; q++) acc[i][j][q] = 0.f;

    int arow = tid >> 1, acol = (tid & 1) * 8;
    const float* aptr = A + (size_t)(bm + arow) * K + acol;
    const float* bptr = B + bn + 4 * lane;

    float ra[8], rb[8];

    // prologue: tile 0 directly to smem buf 0
    {
        float4 v0 = *(const float4*)(aptr);
        float4 v1 = *(const float4*)(aptr + 4);
        As[0][acol+0][arow] = f2tf(v0.x); As[0][acol+1][arow] = f2tf(v0.y);
        As[0][acol+2][arow] = f2tf(v0.z); As[0][acol+3][arow] = f2tf(v0.w);
        As[0][acol+4][arow] = f2tf(v1.x); As[0][acol+5][arow] = f2tf(v1.y);
        As[0][acol+6][arow] = f2tf(v1.z); As[0][acol+7][arow] = f2tf(v1.w);
        #pragma unroll
        for (int r = 0; r < 2; r++) {
            int kr = wid * 2 + r;
            float4 v = *(const float4*)(bptr + (size_t)kr * N);
            uint4 u = { f2tf(v.x), f2tf(v.y), f2tf(v.z), f2tf(v.w) };
            *(uint4*)&Bs[0][kr][4 * lane] = u;
        }
    }

    int nk = K / 16;
    for (int t = 0; t < nk; t++) {
        __syncthreads();
        int cur = t & 1;
        bool more = (t + 1 < nk);
        if (more) {
            int k0 = (t + 1) * 16;
            float4 v0 = *(const float4*)(aptr + k0);
            float4 v1 = *(const float4*)(aptr + k0 + 4);
            ra[0]=v0.x; ra[1]=v0.y; ra[2]=v0.z; ra[3]=v0.w;
            ra[4]=v1.x; ra[5]=v1.y; ra[6]=v1.z; ra[7]=v1.w;
            #pragma unroll
            for (int r = 0; r < 2; r++) {
                int kr = wid * 2 + r;
                float4 v = *(const float4*)(bptr + (size_t)(k0 + kr) * N);
                rb[r*4+0]=v.x; rb[r*4+1]=v.y; rb[r*4+2]=v.z; rb[r*4+3]=v.w;
            }
        }
        // compute on buffer cur
        #pragma unroll
        for (int kk = 0; kk < 16; kk += 8) {
            uint32_t af[4][4], bf[4][2];
            #pragma unroll
            for (int i = 0; i < 4; i++) {
                af[i][0] = As[cur][kk+tig  ][wm + i*16 + gid    ];
                af[i][1] = As[cur][kk+tig  ][wm + i*16 + gid + 8];
                af[i][2] = As[cur][kk+tig+4][wm + i*16 + gid    ];
                af[i][3] = As[cur][kk+tig+4][wm + i*16 + gid + 8];
            }
            #pragma unroll
            for (int j = 0; j < 4; j++) {
                bf[j][0] = Bs[cur][kk+tig  ][wn + j*8 + gid];
                bf[j][1] = Bs[cur][kk+tig+4][wn + j*8 + gid];
            }
            #pragma unroll
            for (int i = 0; i < 4; i++)
                #pragma unroll
                for (int j = 0; j < 4; j++)
                    mma_tf32(acc[i][j], af[i][0], af[i][1], af[i][2], af[i][3],
                             bf[j][0], bf[j][1]);
        }
        if (more) {
            int nxt = cur ^ 1;
            As[nxt][acol+0][arow] = f2tf(ra[0]); As[nxt][acol+1][arow] = f2tf(ra[1]);
            As[nxt][acol+2][arow] = f2tf(ra[2]); As[nxt][acol+3][arow] = f2tf(ra[3]);
            As[nxt][acol+4][arow] = f2tf(ra[4]); As[nxt][acol+5][arow] = f2tf(ra[5]);
            As[nxt][acol+6][arow] = f2tf(ra[6]); As[nxt][acol+7][arow] = f2tf(ra[7]);
            #pragma unroll
            for (int r = 0; r < 2; r++) {
                int kr = wid * 2 + r;
                uint4 u = { f2tf(rb[r*4+0]), f2tf(rb[r*4+1]),
                            f2tf(rb[r*4+2]), f2tf(rb[r*4+3]) };
                *(uint4*)&Bs[nxt][kr][4 * lane] = u;
            }
        }
    }

    // epilogue
    #pragma unroll
    for (int i = 0; i < 4; i++) {
        int r0 = bm + wm + i * 16 + gid;
        #pragma unroll
        for (int j = 0; j < 4; j++) {
            int c0 = bn + wn + j * 8 + tig * 2;
            float v0 = acc[i][j][0], v1 = acc[i][j][1];
            float v2 = acc[i][j][2], v3 = acc[i][j][3];
            if (residual) {
                const float* rr0 = residual + (size_t)r0 * N + c0;
                const float* rr1 = residual + (size_t)(r0 + 8) * N + c0;
                v0 += rr0[0]; v1 += rr0[1]; v2 += rr1[0]; v3 += rr1[1];
            }
            float2 p0 = { v0, v1 }, p1 = { v2, v3 };
            *(float2*)(C + (size_t)r0 * N + c0)       = p0;
            *(float2*)(C + (size_t)(r0 + 8) * N + c0) = p1;
        }
    }
}

// ---------------- causal depthwise conv (K=4) + SiLU ----------------
__global__ void conv_silu_kernel(const float* __restrict__ conv_w,
                                 const float* __restrict__ conv_b) {
    int idx = blockIdx.x * blockDim.x + threadIdx.x;
    if (idx >= TOK * DINNER) return;
    int d = idx & (DINNER - 1);
    int t = idx >> 11;
    int b = t >> 10;
    int l = t & (LSEQ - 1);

    float w0 = conv_w[d * KCONV + 0];
    float w1 = conv_w[d * KCONV + 1];
    float w2 = conv_w[d * KCONV + 2];
    float w3 = conv_w[d * KCONV + 3];
    float acc = conv_b[d];

    const float* base = g_xres + ((size_t)b * LSEQ) * (2 * DINNER) + d;
    if (l - 3 >= 0) acc = fmaf(base[(size_t)(l - 3) * (2 * DINNER)], w0, acc);
    if (l - 2 >= 0) acc = fmaf(base[(size_t)(l - 2) * (2 * DINNER)], w1, acc);
    if (l - 1 >= 0) acc = fmaf(base[(size_t)(l - 1) * (2 * DINNER)], w2, acc);
    acc = fmaf(base[(size_t)l * (2 * DINNER)], w3, acc);

    g_xc[idx] = silu_f(acc);
}

// ---------------- x_proj split-K: g_xc[2048,2048] @ W_x[2048,96] ----------------
// grid (M/64, 4 K-splits), 256 threads, thread tile 4x6.
__global__ void xproj_kernel(const float* __restrict__ Wx) {
    __shared__ float sA[32][68];        // [k][m]
    __shared__ float sW[32][104];       // [k][n]

    int tid = threadIdx.x;
    int bm = blockIdx.x * 64;
    int ks = blockIdx.y;                 // 0..3, K range ks*512..+512
    int tm = tid & 15;                   // rows tm*4..+3
    int tn = tid >> 4;                   // cols tn*6..+5

    float acc[4][6];
    #pragma unroll
    for (int i = 0; i < 4; i++)
        #pragma unroll
        for (int j = 0; j < 6; j++) acc[i][j] = 0.f;

    int lr = tid >> 2;                   // A loader row 0..63
    int lc = (tid & 3) * 8;              // A loader col base

    for (int k0 = ks * 512; k0 < ks * 512 + 512; k0 += 32) {
        // A: 64 rows x 32 k
        {
            const float* src = g_xc + (size_t)(bm + lr) * DINNER + k0 + lc;
            float4 v0 = *(const float4*)src;
            float4 v1 = *(const float4*)(src + 4);
            sA[lc+0][lr]=v0.x; sA[lc+1][lr]=v0.y; sA[lc+2][lr]=v0.z; sA[lc+3][lr]=v0.w;
            sA[lc+4][lr]=v1.x; sA[lc+5][lr]=v1.y; sA[lc+6][lr]=v1.z; sA[lc+7][lr]=v1.w;
        }
        // W: 32 rows x 96 cols = 768 float4, 3 per thread
        #pragma unroll
        for (int q = 0; q < 3; q++) {
            int p = tid + 256 * q;
            int row = p / 24, c4 = p % 24;
            float4 v = *(const float4*)(Wx + (size_t)(k0 + row) * XDBL_N + c4 * 4);
            *(float4*)&sW[row][c4 * 4] = v;
        }
        __syncthreads();
        #pragma unroll 8
        for (int k = 0; k < 32; k++) {
            float4 av = *(const float4*)&sA[k][tm * 4];
            float a[4] = { av.x, av.y, av.z, av.w };
            float2 b0 = *(const float2*)&sW[k][tn * 6];
            float2 b1 = *(const float2*)&sW[k][tn * 6 + 2];
            float2 b2 = *(const float2*)&sW[k][tn * 6 + 4];
            float bv[6] = { b0.x, b0.y, b1.x, b1.y, b2.x, b2.y };
            #pragma unroll
            for (int i = 0; i < 4; i++)
                #pragma unroll
                for (int j = 0; j < 6; j++)
                    acc[i][j] = fmaf(a[i], bv[j], acc[i][j]);
        }
        __syncthreads();
    }
    float* dst = g_xp + (size_t)ks * TOK * XDBL_N;
    #pragma unroll
    for (int i = 0; i < 4; i++)
        #pragma unroll
        for (int j = 0; j < 6; j++)
            dst[(size_t)(bm + tm * 4 + i) * XDBL_N + tn * 6 + j] = acc[i][j];
}

__global__ void xproj_reduce() {
    int idx = blockIdx.x * blockDim.x + threadIdx.x;
    if (idx >= TOK * XDBL_N) return;
    float s = g_xp[idx] + g_xp[TOK*XDBL_N + idx]
            + g_xp[2*TOK*XDBL_N + idx] + g_xp[3*TOK*XDBL_N + idx];
    g_xdbl[idx] = s;
}

// ---------------- delta = softplus(dlt @ W_dt + b_dt), 4 tokens/block --------
__global__ void delta_kernel(const float* __restrict__ W_dt,
                             const float* __restrict__ b_dt) {
    __shared__ float sd[4][DTRANK];
    int tid = threadIdx.x;
    int t0 = blockIdx.x * 4;
    if (tid < 256) {  // 4*64 = 256 loads
        int tok = tid >> 6, k = tid & 63;
        sd[tok][k] = g_xdbl[(size_t)(t0 + tok) * XDBL_N + k];
    }
    __syncthreads();

    float bb[8];
    #pragma unroll
    for (int j = 0; j < 8; j++) bb[j] = b_dt[tid + 256 * j];
    float acc[4][8];
    #pragma unroll
    for (int tok = 0; tok < 4; tok++)
        #pragma unroll
        for (int j = 0; j < 8; j++) acc[tok][j] = bb[j];

    #pragma unroll 4
    for (int k = 0; k < DTRANK; k++) {
        float w[8];
        #pragma unroll
        for (int j = 0; j < 8; j++) w[j] = W_dt[(size_t)k * DINNER + tid + 256 * j];
        #pragma unroll
        for (int tok = 0; tok < 4; tok++) {
            float dl = sd[tok][k];
            #pragma unroll
            for (int j = 0; j < 8; j++) acc[tok][j] = fmaf(dl, w[j], acc[tok][j]);
        }
    }
    #pragma unroll
    for (int tok = 0; tok < 4; tok++)
        #pragma unroll
        for (int j = 0; j < 8; j++) {
            float x = acc[tok][j];
            float sp = (x > 20.f) ? x : log1pf(__expf(x));
            g_delta[(size_t)(t0 + tok) * DINNER + tid + 256 * j] = sp;
        }
}

// ---------------- scan pass A: chunk-local states + dA products ----------------
__global__ void scanA_kernel(const float* __restrict__ A) {
    int g = blockIdx.x * blockDim.x + threadIdx.x;   // (b*NC + c)*DINNER + d
    int d  = g & (DINNER - 1);
    int bc = g >> 11;
    int c  = bc & (NCHUNK - 1);
    int b  = bc >> 5;

    float a[DSTATE], s[DSTATE], P[DSTATE];
    #pragma unroll
    for (int q = 0; q < 4; q++) {
        float4 v = *(const float4*)(A + d * DSTATE + q * 4);
        a[q*4+0]=v.x; a[q*4+1]=v.y; a[q*4+2]=v.z; a[q*4+3]=v.w;
    }
    #pragma unroll
    for (int n = 0; n < DSTATE; n++) { s[n] = 0.f; P[n] = 1.f; }

    int t0 = b * LSEQ + c * CLEN;
    for (int l = 0; l < CLEN; l++) {
        int t = t0 + l;
        float delta = g_delta[(size_t)t * DINNER + d];
        float xv    = g_xc   [(size_t)t * DINNER + d];
        float du    = delta * xv;
        const float* Bv = g_xdbl + (size_t)t * XDBL_N + DTRANK;
        #pragma unroll
        for (int n = 0; n < DSTATE; n++) {
            float dA = __expf(delta * a[n]);
            s[n] = fmaf(dA, s[n], du * Bv[n]);
            P[n] *= dA;
        }
    }
    float* Sp = g_S + (size_t)bc * (DINNER * DSTATE) + d * DSTATE;
    float* Pp = g_P + (size_t)bc * (DINNER * DSTATE) + d * DSTATE;
    #pragma unroll
    for (int q = 0; q < 4; q++) {
        float4 vs = { s[q*4+0], s[q*4+1], s[q*4+2], s[q*4+3] };
        float4 vp = { P[q*4+0], P[q*4+1], P[q*4+2], P[q*4+3] };
        *(float4*)(Sp + q * 4) = vs;
        *(float4*)(Pp + q * 4) = vp;
    }
}

// ---------------- scan pass B: sequential chunk combine ----------------
__global__ void scanB_kernel() {
    int g = blockIdx.x * blockDim.x + threadIdx.x;   // b*DN + idx
    int idx = g & (DN - 1);
    int b   = g >> 15;
    size_t base = (size_t)b * NCHUNK * DN;
    float s = 0.f;
    for (int c = 0; c < NCHUNK; c++) {
        size_t o = base + (size_t)c * DN + idx;
        g_SI[o] = s;
        s = g_S[o] + g_P[o] * s;
    }
}

// ---------------- scan pass C: replay with init, output gated y ----------------
__global__ void scanC_kernel(const float* __restrict__ A,
                             const float* __restrict__ Dp) {
    int g = blockIdx.x * blockDim.x + threadIdx.x;
    int d  = g & (DINNER - 1);
    int bc = g >> 11;
    int c  = bc & (NCHUNK - 1);
    int b  = bc >> 5;

    float a[DSTATE], s[DSTATE];
    #pragma unroll
    for (int q = 0; q < 4; q++) {
        float4 v = *(const float4*)(A + d * DSTATE + q * 4);
        a[q*4+0]=v.x; a[q*4+1]=v.y; a[q*4+2]=v.z; a[q*4+3]=v.w;
        float4 vi = *(const float4*)(g_SI + (size_t)bc * DN + d * DSTATE + q * 4);
        s[q*4+0]=vi.x; s[q*4+1]=vi.y; s[q*4+2]=vi.z; s[q*4+3]=vi.w;
    }
    float Dd = Dp[d];

    int t0 = b * LSEQ + c * CLEN;
    for (int l = 0; l < CLEN; l++) {
        int t = t0 + l;
        float delta = g_delta[(size_t)t * DINNER + d];
        float xv    = g_xc   [(size_t)t * DINNER + d];
        float du    = delta * xv;
        const float* Bv = g_xdbl + (size_t)t * XDBL_N + DTRANK;
        const float* Cv = Bv + DSTATE;
        float y = 0.f;
        #pragma unroll
        for (int n = 0; n < DSTATE; n++) {
            float dA = __expf(delta * a[n]);
            s[n] = fmaf(dA, s[n], du * Bv[n]);
            y = fmaf(s[n], Cv[n], y);
        }
        float res = g_xres[(size_t)t * (2 * DINNER) + DINNER + d];
        g_y[(size_t)t * DINNER + d] = (y + xv * Dd) * silu_f(res);
    }
}

// ---------------- launch ----------------
extern "C" void kernel_launch(void* const* d_in, const int* in_sizes, int n_in,
                              void* d_out, int out_size) {
    const float* x0     = (const float*)d_in[0];
    const float* norm_w = (const float*)d_in[1];
    const float* W_in   = (const float*)d_in[2];
    const float* conv_w = (const float*)d_in[3];
    const float* conv_b = (const float*)d_in[4];
    const float* W_x    = (const float*)d_in[5];
    const float* W_dt   = (const float*)d_in[6];
    const float* b_dt   = (const float*)d_in[7];
    const float* Amat   = (const float*)d_in[8];
    const float* Dvec   = (const float*)d_in[9];
    const float* W_out  = (const float*)d_in[10];
    float* out = (float*)d_out;

    float *p_h, *p_xres, *p_y;
    cudaGetSymbolAddress((void**)&p_h,    g_h);
    cudaGetSymbolAddress((void**)&p_xres, g_xres);
    cudaGetSymbolAddress((void**)&p_y,    g_y);

    // 1) RMSNorm
    rmsnorm_kernel<<<TOK, 256>>>(x0, norm_w);

    // 2) in_proj (tf32 mma): [2048,1024] @ [1024,4096]
    mma_gemm<<<dim3(4096 / 128, TOK / 128), 256>>>(
        p_h, W_in, p_xres, TOK, 2 * DINNER, DMODEL, nullptr);

    // 3) conv + silu
    conv_silu_kernel<<<(TOK * DINNER) / 256, 256>>>(conv_w, conv_b);

    // 4) x_proj split-K + reduce
    xproj_kernel<<<dim3(TOK / 64, 4), 256>>>(W_x);
    xproj_reduce<<<(TOK * XDBL_N) / 256, 256>>>();

    // 5) delta
    delta_kernel<<<TOK / 4, 256>>>(W_dt, b_dt);

    // 6) chunked selective scan
    scanA_kernel<<<(BATCH * NCHUNK * DINNER) / 256, 256>>>(Amat);
    scanB_kernel<<<(BATCH * DN) / 256, 256>>>();
    scanC_kernel<<<(BATCH * NCHUNK * DINNER) / 256, 256>>>(Amat, Dvec);

    // 7) out_proj (tf32 mma) + residual
    mma_gemm<<<dim3(DMODEL / 128, TOK / 128), 256>>>(
        p_y, W_out, out, TOK, DMODEL, DINNER, x0);
}

// round 3
// speedup vs baseline: 5.2153x; 1.0832x over previous
#include <cuda_runtime.h>
#include <math.h>
#include <stdint.h>

// ---------------- problem constants ----------------
#define BATCH   2
#define LSEQ    1024
#define DMODEL  1024
#define DINNER  2048
#define DSTATE  16
#define DTRANK  64
#define KCONV   4
#define TOK     (BATCH*LSEQ)        // 2048 tokens
#define XDBL_N  (DTRANK + 2*DSTATE) // 96
#define EPS     1e-5f

#define NCHUNK  32
#define CLEN    (LSEQ/NCHUNK)       // 32
#define DN      (DINNER*DSTATE)     // 32768
#define NSPLIT  16                  // x_proj K splits

// ---------------- scratch ----------------
__device__ float g_h    [TOK * DMODEL];
__device__ float g_xres [TOK * 2 * DINNER];
__device__ float g_xc   [TOK * DINNER];
__device__ float g_xdbl [TOK * XDBL_N];
__device__ float g_delta[TOK * DINNER];
__device__ float g_y    [TOK * DINNER];
__device__ float g_xp   [NSPLIT * TOK * XDBL_N];
__device__ float g_S    [BATCH * NCHUNK * DN];
__device__ float g_P    [BATCH * NCHUNK * DN];
__device__ float g_SI   [BATCH * NCHUNK * DN];

// ---------------- helpers ----------------
__device__ __forceinline__ void mma_tf32(float c[4],
    uint32_t a0, uint32_t a1, uint32_t a2, uint32_t a3,
    uint32_t b0, uint32_t b1) {
    asm volatile(
        "mma.sync.aligned.m16n8k8.row.col.f32.tf32.tf32.f32 "
        "{%0,%1,%2,%3}, {%4,%5,%6,%7}, {%8,%9}, {%0,%1,%2,%3};"
        : "+f"(c[0]), "+f"(c[1]), "+f"(c[2]), "+f"(c[3])
        : "r"(a0), "r"(a1), "r"(a2), "r"(a3), "r"(b0), "r"(b1));
}
__device__ __forceinline__ float silu_f(float x) {
    return x / (1.f + __expf(-x));
}
__device__ __forceinline__ void cp16(uint32_t smem, const void* g) {
    asm volatile("cp.async.cg.shared.global [%0], [%1], 16;\n" :: "r"(smem), "l"(g));
}

// ---------------- RMSNorm ----------------
__global__ void rmsnorm_kernel(const float* __restrict__ x0,
                               const float* __restrict__ w) {
    int t = blockIdx.x;
    const float* xr = x0 + (size_t)t * DMODEL;
    float s = 0.f;
    #pragma unroll
    for (int i = 0; i < DMODEL / 256; i++) {
        float v = xr[threadIdx.x + i * 256];
        s += v * v;
    }
    #pragma unroll
    for (int o = 16; o > 0; o >>= 1) s += __shfl_xor_sync(0xffffffffu, s, o);
    __shared__ float ws[8];
    if ((threadIdx.x & 31) == 0) ws[threadIdx.x >> 5] = s;
    __syncthreads();
    if (threadIdx.x < 8) {
        float v = ws[threadIdx.x];
        #pragma unroll
        for (int o = 4; o > 0; o >>= 1) v += __shfl_xor_sync(0xffu, v, o);
        if (threadIdx.x == 0) ws[0] = v;
    }
    __syncthreads();
    float rs = rsqrtf(ws[0] / (float)DMODEL + EPS);
    float* hr = g_h + (size_t)t * DMODEL;
    #pragma unroll
    for (int i = 0; i < DMODEL / 256; i++) {
        int c = threadIdx.x + i * 256;
        hr[c] = xr[c] * rs * w[c];
    }
}

// ---------------- TF32 MMA GEMM v2 ----------------
// 128x128 tile, BK=16, 256 threads (8 warps 2x4), warp tile 64x32.
// A: LDG->STS into k-paired layout (LDS.64 operand reads, conflict-free).
// B: cp.async 16B into [k][136] layout (conflict-free LDS.32 reads).
// Raw fp32 bits fed to HMMA (tf32 truncation).
#define AP2 140   // float2 pitch for A m-dimension

__global__ void __launch_bounds__(256)
mma_gemm(const float* __restrict__ A, const float* __restrict__ B,
         float* __restrict__ C, int M, int N, int K,
         const float* __restrict__ residual) {
    // As[buf][g][tig][m*2 + s] ; g = k>>3, tig = k&3, s = (k>>2)&1
    __shared__ float As[2][2][4][AP2 * 2];
    __shared__ float Bs[2][16][136];

    int tid  = threadIdx.x;
    int lane = tid & 31, wid = tid >> 5;
    int bm = blockIdx.y * 128, bn = blockIdx.x * 128;
    int wm = (wid >> 2) * 64, wn = (wid & 3) * 32;
    int gid = lane >> 2, tig = lane & 3;

    float acc[4][4][4];
    #pragma unroll
    for (int i = 0; i < 4; i++)
        #pragma unroll
        for (int j = 0; j < 4; j++)
            #pragma unroll
            for (int q = 0; q < 4; q++) acc[i][j][q] = 0.f;

    int arow = tid >> 1;
    int ag   = tid & 1;            // g for this thread's A chunk (acol = ag*8)
    const float* aptr = A + (size_t)(bm + arow) * K + ag * 8;

    // B cp.async mapping: chunk p in [0,512): row=p>>5, c4=p&31
    int p0r = tid >> 5,          p0c = tid & 31;
    int p1r = (tid + 256) >> 5,  p1c = tid & 31;
    const float* bbase = B + bn;

    uint32_t sB0a = (uint32_t)__cvta_generic_to_shared(&Bs[0][p0r][p0c * 4]);
    uint32_t sB1a = (uint32_t)__cvta_generic_to_shared(&Bs[0][p1r][p1c * 4]);
    uint32_t sBstride = (uint32_t)((char*)&Bs[1][0][0] - (char*)&Bs[0][0][0]);

    float ra[8];

    // ---- prologue: stage 0 ----
    {
        float4 v0 = *(const float4*)(aptr);
        float4 v1 = *(const float4*)(aptr + 4);
        ra[0]=v0.x; ra[1]=v0.y; ra[2]=v0.z; ra[3]=v0.w;
        ra[4]=v1.x; ra[5]=v1.y; ra[6]=v1.z; ra[7]=v1.w;
        #pragma unroll
        for (int j = 0; j < 4; j++) {
            float2 pr = { ra[j], ra[j + 4] };
            *(float2*)&As[0][ag][j][arow * 2] = pr;
        }
        cp16(sB0a, bbase + (size_t)p0r * N + p0c * 4);
        cp16(sB1a, bbase + (size_t)p1r * N + p1c * 4);
        asm volatile("cp.async.commit_group;\n");
        asm volatile("cp.async.wait_group 0;\n" ::: "memory");
        __syncthreads();
    }

    int nk = K / 16;
    for (int t = 0; t < nk; t++) {
        int cur = t & 1, nxt = cur ^ 1;
        bool more = (t + 1 < nk);
        if (more) {
            int k0 = (t + 1) * 16;
            float4 v0 = *(const float4*)(aptr + k0);
            float4 v1 = *(const float4*)(aptr + k0 + 4);
            ra[0]=v0.x; ra[1]=v0.y; ra[2]=v0.z; ra[3]=v0.w;
            ra[4]=v1.x; ra[5]=v1.y; ra[6]=v1.z; ra[7]=v1.w;
            uint32_t off = nxt ? sBstride : 0u;
            cp16(sB0a + off, bbase + (size_t)(k0 + p0r) * N + p0c * 4);
            cp16(sB1a + off, bbase + (size_t)(k0 + p1r) * N + p1c * 4);
            asm volatile("cp.async.commit_group;\n");
        }
        // ---- compute on buffer cur ----
        #pragma unroll
        for (int kk = 0; kk < 16; kk += 8) {
            int g = kk >> 3;
            float2 a02[4], a13[4];
            uint32_t bf[4][2];
            #pragma unroll
            for (int i = 0; i < 4; i++) {
                int m = wm + i * 16 + gid;
                a02[i] = *(const float2*)&As[cur][g][tig][m * 2];
                a13[i] = *(const float2*)&As[cur][g][tig][(m + 8) * 2];
            }
            #pragma unroll
            for (int j = 0; j < 4; j++) {
                bf[j][0] = __float_as_uint(Bs[cur][kk + tig    ][wn + j * 8 + gid]);
                bf[j][1] = __float_as_uint(Bs[cur][kk + tig + 4][wn + j * 8 + gid]);
            }
            #pragma unroll
            for (int i = 0; i < 4; i++)
                #pragma unroll
                for (int j = 0; j < 4; j++)
                    mma_tf32(acc[i][j],
                             __float_as_uint(a02[i].x), __float_as_uint(a13[i].x),
                             __float_as_uint(a02[i].y), __float_as_uint(a13[i].y),
                             bf[j][0], bf[j][1]);
        }
        if (more) {
            #pragma unroll
            for (int j = 0; j < 4; j++) {
                float2 pr = { ra[j], ra[j + 4] };
                *(float2*)&As[nxt][ag][j][arow * 2] = pr;
            }
            asm volatile("cp.async.wait_group 0;\n" ::: "memory");
            __syncthreads();
        }
    }

    // ---- epilogue ----
    #pragma unroll
    for (int i = 0; i < 4; i++) {
        int r0 = bm + wm + i * 16 + gid;
        #pragma unroll
        for (int j = 0; j < 4; j++) {
            int c0 = bn + wn + j * 8 + tig * 2;
            float v0 = acc[i][j][0], v1 = acc[i][j][1];
            float v2 = acc[i][j][2], v3 = acc[i][j][3];
            if (residual) {
                const float* rr0 = residual + (size_t)r0 * N + c0;
                const float* rr1 = residual + (size_t)(r0 + 8) * N + c0;
                v0 += rr0[0]; v1 += rr0[1]; v2 += rr1[0]; v3 += rr1[1];
            }
            float2 q0 = { v0, v1 }, q1 = { v2, v3 };
            *(float2*)(C + (size_t)r0 * N + c0)       = q0;
            *(float2*)(C + (size_t)(r0 + 8) * N + c0) = q1;
        }
    }
}

// ---------------- causal depthwise conv (K=4) + SiLU, 4 outputs/thread ------
__global__ void conv_silu_kernel(const float* __restrict__ conv_w,
                                 const float* __restrict__ conv_b) {
    int gidx = blockIdx.x * blockDim.x + threadIdx.x;   // (b, l0/4, d)
    int d  = gidx & (DINNER - 1);
    int q  = gidx >> 11;
    int l4 = q & (LSEQ / 4 - 1);
    int b  = q >> 8;
    int l0 = l4 * 4;

    float w0 = conv_w[d * KCONV + 0];
    float w1 = conv_w[d * KCONV + 1];
    float w2 = conv_w[d * KCONV + 2];
    float w3 = conv_w[d * KCONV + 3];
    float cb = conv_b[d];

    const size_t S = 2 * DINNER;
    const float* base = g_xres + (size_t)(b * LSEQ) * S + d;

    float h0 = 0.f, h1 = 0.f, h2 = 0.f;
    if (l0 > 0) {
        h0 = base[(size_t)(l0 - 3) * S];
        h1 = base[(size_t)(l0 - 2) * S];
        h2 = base[(size_t)(l0 - 1) * S];
    }
    float c0 = base[(size_t)(l0 + 0) * S];
    float c1 = base[(size_t)(l0 + 1) * S];
    float c2 = base[(size_t)(l0 + 2) * S];
    float c3 = base[(size_t)(l0 + 3) * S];

    float o0 = fmaf(w0,h0, fmaf(w1,h1, fmaf(w2,h2, fmaf(w3,c0, cb))));
    float o1 = fmaf(w0,h1, fmaf(w1,h2, fmaf(w2,c0, fmaf(w3,c1, cb))));
    float o2 = fmaf(w0,h2, fmaf(w1,c0, fmaf(w2,c1, fmaf(w3,c2, cb))));
    float o3 = fmaf(w0,c0, fmaf(w1,c1, fmaf(w2,c2, fmaf(w3,c3, cb))));

    size_t t0 = (size_t)(b * LSEQ + l0) * DINNER + d;
    g_xc[t0]              = silu_f(o0);
    g_xc[t0 + DINNER]     = silu_f(o1);
    g_xc[t0 + 2 * DINNER] = silu_f(o2);
    g_xc[t0 + 3 * DINNER] = silu_f(o3);
}

// ---------------- x_proj split-K (16 splits) ----------------
__global__ void xproj_kernel(const float* __restrict__ Wx) {
    __shared__ float sA[32][68];
    __shared__ float sW[32][104];

    int tid = threadIdx.x;
    int bm = blockIdx.x * 64;
    int ks = blockIdx.y;                 // 0..15, K range ks*128..+128
    int tm = tid & 15;
    int tn = tid >> 4;

    float acc[4][6];
    #pragma unroll
    for (int i = 0; i < 4; i++)
        #pragma unroll
        for (int j = 0; j < 6; j++) acc[i][j] = 0.f;

    int lr = tid >> 2;
    int lc = (tid & 3) * 8;

    for (int k0 = ks * 128; k0 < ks * 128 + 128; k0 += 32) {
        {
            const float* src = g_xc + (size_t)(bm + lr) * DINNER + k0 + lc;
            float4 v0 = *(const float4*)src;
            float4 v1 = *(const float4*)(src + 4);
            sA[lc+0][lr]=v0.x; sA[lc+1][lr]=v0.y; sA[lc+2][lr]=v0.z; sA[lc+3][lr]=v0.w;
            sA[lc+4][lr]=v1.x; sA[lc+5][lr]=v1.y; sA[lc+6][lr]=v1.z; sA[lc+7][lr]=v1.w;
        }
        #pragma unroll
        for (int q = 0; q < 3; q++) {
            int p = tid + 256 * q;
            int row = p / 24, c4 = p % 24;
            float4 v = *(const float4*)(Wx + (size_t)(k0 + row) * XDBL_N + c4 * 4);
            *(float4*)&sW[row][c4 * 4] = v;
        }
        __syncthreads();
        #pragma unroll 8
        for (int k = 0; k < 32; k++) {
            float4 av = *(const float4*)&sA[k][tm * 4];
            float a[4] = { av.x, av.y, av.z, av.w };
            float2 b0 = *(const float2*)&sW[k][tn * 6];
            float2 b1 = *(const float2*)&sW[k][tn * 6 + 2];
            float2 b2 = *(const float2*)&sW[k][tn * 6 + 4];
            float bv[6] = { b0.x, b0.y, b1.x, b1.y, b2.x, b2.y };
            #pragma unroll
            for (int i = 0; i < 4; i++)
                #pragma unroll
                for (int j = 0; j < 6; j++)
                    acc[i][j] = fmaf(a[i], bv[j], acc[i][j]);
        }
        __syncthreads();
    }
    float* dst = g_xp + (size_t)ks * TOK * XDBL_N;
    #pragma unroll
    for (int i = 0; i < 4; i++)
        #pragma unroll
        for (int j = 0; j < 6; j++)
            dst[(size_t)(bm + tm * 4 + i) * XDBL_N + tn * 6 + j] = acc[i][j];
}

__global__ void xproj_reduce() {
    int idx = blockIdx.x * blockDim.x + threadIdx.x;
    if (idx >= TOK * XDBL_N) return;
    float s = 0.f;
    #pragma unroll
    for (int q = 0; q < NSPLIT; q++)
        s += g_xp[(size_t)q * TOK * XDBL_N + idx];
    g_xdbl[idx] = s;
}

// ---------------- delta = softplus(dlt @ W_dt + b_dt), 8 tokens/block --------
__global__ void delta_kernel(const float* __restrict__ W_dt,
                             const float* __restrict__ b_dt) {
    __shared__ float sd[8][DTRANK];
    int tid = threadIdx.x;
    int t0 = blockIdx.x * 8;
    #pragma unroll
    for (int q = 0; q < 2; q++) {
        int p = tid + 256 * q;
        int tok = p >> 6, k = p & 63;
        sd[tok][k] = g_xdbl[(size_t)(t0 + tok) * XDBL_N + k];
    }
    __syncthreads();

    float bb[8];
    #pragma unroll
    for (int j = 0; j < 8; j++) bb[j] = b_dt[tid + 256 * j];
    float acc[8][8];
    #pragma unroll
    for (int tok = 0; tok < 8; tok++)
        #pragma unroll
        for (int j = 0; j < 8; j++) acc[tok][j] = bb[j];

    #pragma unroll 4
    for (int k = 0; k < DTRANK; k++) {
        float w[8];
        #pragma unroll
        for (int j = 0; j < 8; j++) w[j] = W_dt[(size_t)k * DINNER + tid + 256 * j];
        #pragma unroll
        for (int tok = 0; tok < 8; tok++) {
            float dl = sd[tok][k];
            #pragma unroll
            for (int j = 0; j < 8; j++) acc[tok][j] = fmaf(dl, w[j], acc[tok][j]);
        }
    }
    #pragma unroll
    for (int tok = 0; tok < 8; tok++)
        #pragma unroll
        for (int j = 0; j < 8; j++) {
            float x = acc[tok][j];
            float sp = (x > 20.f) ? x : log1pf(__expf(x));
            g_delta[(size_t)(t0 + tok) * DINNER + tid + 256 * j] = sp;
        }
}

// ---------------- scan pass A ----------------
__global__ void scanA_kernel(const float* __restrict__ A) {
    int g = blockIdx.x * blockDim.x + threadIdx.x;
    int d  = g & (DINNER - 1);
    int bc = g >> 11;
    int c  = bc & (NCHUNK - 1);
    int b  = bc >> 5;

    float a[DSTATE], s[DSTATE], P[DSTATE];
    #pragma unroll
    for (int q = 0; q < 4; q++) {
        float4 v = *(const float4*)(A + d * DSTATE + q * 4);
        a[q*4+0]=v.x; a[q*4+1]=v.y; a[q*4+2]=v.z; a[q*4+3]=v.w;
    }
    #pragma unroll
    for (int n = 0; n < DSTATE; n++) { s[n] = 0.f; P[n] = 1.f; }

    int t0 = b * LSEQ + c * CLEN;
    for (int l = 0; l < CLEN; l++) {
        int t = t0 + l;
        float delta = g_delta[(size_t)t * DINNER + d];
        float xv    = g_xc   [(size_t)t * DINNER + d];
        float du    = delta * xv;
        const float* Bv = g_xdbl + (size_t)t * XDBL_N + DTRANK;
        #pragma unroll
        for (int n = 0; n < DSTATE; n++) {
            float dA = __expf(delta * a[n]);
            s[n] = fmaf(dA, s[n], du * Bv[n]);
            P[n] *= dA;
        }
    }
    float* Sp = g_S + (size_t)bc * DN + d * DSTATE;
    float* Pp = g_P + (size_t)bc * DN + d * DSTATE;
    #pragma unroll
    for (int q = 0; q < 4; q++) {
        float4 vs = { s[q*4+0], s[q*4+1], s[q*4+2], s[q*4+3] };
        float4 vp = { P[q*4+0], P[q*4+1], P[q*4+2], P[q*4+3] };
        *(float4*)(Sp + q * 4) = vs;
        *(float4*)(Pp + q * 4) = vp;
    }
}

// ---------------- scan pass B ----------------
__global__ void scanB_kernel() {
    int g = blockIdx.x * blockDim.x + threadIdx.x;
    int idx = g & (DN - 1);
    int b   = g >> 15;
    size_t base = (size_t)b * NCHUNK * DN;
    float s = 0.f;
    for (int c = 0; c < NCHUNK; c++) {
        size_t o = base + (size_t)c * DN + idx;
        g_SI[o] = s;
        s = g_S[o] + g_P[o] * s;
    }
}

// ---------------- scan pass C ----------------
__global__ void scanC_kernel(const float* __restrict__ A,
                             const float* __restrict__ Dp) {
    int g = blockIdx.x * blockDim.x + threadIdx.x;
    int d  = g & (DINNER - 1);
    int bc = g >> 11;
    int c  = bc & (NCHUNK - 1);
    int b  = bc >> 5;

    float a[DSTATE], s[DSTATE];
    #pragma unroll
    for (int q = 0; q < 4; q++) {
        float4 v = *(const float4*)(A + d * DSTATE + q * 4);
        a[q*4+0]=v.x; a[q*4+1]=v.y; a[q*4+2]=v.z; a[q*4+3]=v.w;
        float4 vi = *(const float4*)(g_SI + (size_t)bc * DN + d * DSTATE + q * 4);
        s[q*4+0]=vi.x; s[q*4+1]=vi.y; s[q*4+2]=vi.z; s[q*4+3]=vi.w;
    }
    float Dd = Dp[d];

    int t0 = b * LSEQ + c * CLEN;
    for (int l = 0; l < CLEN; l++) {
        int t = t0 + l;
        float delta = g_delta[(size_t)t * DINNER + d];
        float xv    = g_xc   [(size_t)t * DINNER + d];
        float du    = delta * xv;
        const float* Bv = g_xdbl + (size_t)t * XDBL_N + DTRANK;
        const float* Cv = Bv + DSTATE;
        float y = 0.f;
        #pragma unroll
        for (int n = 0; n < DSTATE; n++) {
            float dA = __expf(delta * a[n]);
            s[n] = fmaf(dA, s[n], du * Bv[n]);
            y = fmaf(s[n], Cv[n], y);
        }
        float res = g_xres[(size_t)t * (2 * DINNER) + DINNER + d];
        g_y[(size_t)t * DINNER + d] = (y + xv * Dd) * silu_f(res);
    }
}

// ---------------- launch ----------------
extern "C" void kernel_launch(void* const* d_in, const int* in_sizes, int n_in,
                              void* d_out, int out_size) {
    const float* x0     = (const float*)d_in[0];
    const float* norm_w = (const float*)d_in[1];
    const float* W_in   = (const float*)d_in[2];
    const float* conv_w = (const float*)d_in[3];
    const float* conv_b = (const float*)d_in[4];
    const float* W_x    = (const float*)d_in[5];
    const float* W_dt   = (const float*)d_in[6];
    const float* b_dt   = (const float*)d_in[7];
    const float* Amat   = (const float*)d_in[8];
    const float* Dvec   = (const float*)d_in[9];
    const float* W_out  = (const float*)d_in[10];
    float* out = (float*)d_out;

    float *p_h, *p_xres, *p_y;
    cudaGetSymbolAddress((void**)&p_h,    g_h);
    cudaGetSymbolAddress((void**)&p_xres, g_xres);
    cudaGetSymbolAddress((void**)&p_y,    g_y);

    rmsnorm_kernel<<<TOK, 256>>>(x0, norm_w);

    mma_gemm<<<dim3(4096 / 128, TOK / 128), 256>>>(
        p_h, W_in, p_xres, TOK, 2 * DINNER, DMODEL, nullptr);

    conv_silu_kernel<<<(TOK / 4 * DINNER) / 256, 256>>>(conv_w, conv_b);

    xproj_kernel<<<dim3(TOK / 64, NSPLIT), 256>>>(W_x);
    xproj_reduce<<<(TOK * XDBL_N) / 256, 256>>>();

    delta_kernel<<<TOK / 8, 256>>>(W_dt, b_dt);

    scanA_kernel<<<(BATCH * NCHUNK * DINNER) / 256, 256>>>(Amat);
    scanB_kernel<<<(BATCH * DN) / 256, 256>>>();
    scanC_kernel<<<(BATCH * NCHUNK * DINNER) / 256, 256>>>(Amat, Dvec);

    mma_gemm<<<dim3(DMODEL / 128, TOK / 128), 256>>>(
        p_y, W_out, out, TOK, DMODEL, DINNER, x0);
}

// round 5
// speedup vs baseline: 7.4446x; 1.4275x over previous
#include <cuda_runtime.h>
#include <cuda_bf16.h>
#include <math.h>
#include <stdint.h>

// ---------------- problem constants ----------------
#define BATCH   2
#define LSEQ    1024
#define DMODEL  1024
#define DINNER  2048
#define DSTATE  16
#define DTRANK  64
#define KCONV   4
#define TOK     (BATCH*LSEQ)        // 2048 tokens
#define XDBL_N  (DTRANK + 2*DSTATE) // 96
#define EPS     1e-5f

#define NCHUNK  32
#define CLEN    (LSEQ/NCHUNK)       // 32
#define DN      (DINNER*DSTATE)     // 32768
#define NSPLIT  16

// ---------------- scratch ----------------
__device__ __align__(16) __nv_bfloat16 g_hb   [TOK * DMODEL];        // rmsnorm out (bf16)
__device__ __align__(16) __nv_bfloat16 g_yb   [TOK * DINNER];        // scan out (bf16)
__device__ __align__(16) __nv_bfloat16 g_wint [2*DINNER * DMODEL];   // W_in^T  [4096][1024]
__device__ __align__(16) __nv_bfloat16 g_woutt[DMODEL * DINNER];     // W_out^T [1024][2048]
__device__ __align__(16) float g_xres [TOK * 2 * DINNER];
__device__ __align__(16) float g_xc   [TOK * DINNER];
__device__ __align__(16) float g_xdbl [TOK * XDBL_N];
__device__ __align__(16) float g_delta[TOK * DINNER];
__device__ __align__(16) float g_xp   [NSPLIT * TOK * XDBL_N];
__device__ __align__(16) float g_S    [BATCH * NCHUNK * DN];
__device__ __align__(16) float g_P    [BATCH * NCHUNK * DN];
__device__ __align__(16) float g_SI   [BATCH * NCHUNK * DN];

// ---------------- helpers ----------------
__device__ __forceinline__ float silu_f(float x) {
    return x / (1.f + __expf(-x));
}
__device__ __forceinline__ void cp16(uint32_t smem, const void* g) {
    asm volatile("cp.async.cg.shared.global [%0], [%1], 16;\n" :: "r"(smem), "l"(g));
}
__device__ __forceinline__ void mma_bf16(float c[4],
    uint32_t a0, uint32_t a1, uint32_t a2, uint32_t a3,
    uint32_t b0, uint32_t b1) {
    asm volatile(
        "mma.sync.aligned.m16n8k16.row.col.f32.bf16.bf16.f32 "
        "{%0,%1,%2,%3}, {%4,%5,%6,%7}, {%8,%9}, {%0,%1,%2,%3};"
        : "+f"(c[0]), "+f"(c[1]), "+f"(c[2]), "+f"(c[3])
        : "r"(a0), "r"(a1), "r"(a2), "r"(a3), "r"(b0), "r"(b1));
}
__device__ __forceinline__ void ldmx4(uint32_t r[4], uint32_t addr) {
    asm volatile(
        "ldmatrix.sync.aligned.m8n8.x4.shared.b16 {%0,%1,%2,%3}, [%4];"
        : "=r"(r[0]), "=r"(r[1]), "=r"(r[2]), "=r"(r[3]) : "r"(addr));
}

// ---------------- bf16 MMA GEMM ----------------
// C[M,N] = A[M,K](bf16 row-major) @ Bt[N,K](bf16 row-major)^T (+residual), fp32 out.
// CTA tile 128x128, BK=64, 256 threads (8 warps 2x4), warp tile 64x32.
// SMEM: 128B rows (64 bf16), SW128 swizzle, double-buffered. ldmatrix operands.
#define GSTG   16384u                     // one A or B stage: 128 rows * 128B
#define GEMM_SMEM (4 * GSTG)              // A0,A1,B0,B1 = 64 KB

__global__ void __launch_bounds__(256)
gemm_bf16(const __nv_bfloat16* __restrict__ A, const __nv_bfloat16* __restrict__ Bt,
          float* __restrict__ C, int M, int N, int K,
          const float* __restrict__ residual) {
    extern __shared__ char smem[];
    uint32_t smem_base;
    asm("{ .reg .u64 t; cvta.to.shared.u64 t, %1; cvt.u32.u64 %0, t; }"
        : "=r"(smem_base) : "l"(smem));

    int tid  = threadIdx.x;
    int lane = tid & 31, wid = tid >> 5;
    int bm = blockIdx.y * 128, bn = blockIdx.x * 128;
    int wm = (wid >> 2) * 64, wn = (wid & 3) * 32;
    int gid = lane >> 2, tig = lane & 3;

    float acc[4][4][4];
    #pragma unroll
    for (int i = 0; i < 4; i++)
        #pragma unroll
        for (int j = 0; j < 4; j++)
            #pragma unroll
            for (int q = 0; q < 4; q++) acc[i][j][q] = 0.f;

    const __nv_bfloat16* abase = A + (size_t)bm * K;
    const __nv_bfloat16* bbase = Bt + (size_t)bn * K;

    // loader: 1024 chunks of 16B per stage per matrix; 4 per thread each
    int lrow = tid >> 3;            // base row 0..31 (advance by 32)
    int lch  = tid & 7;             // 16B chunk 0..7 within row
    uint32_t sw_off = (uint32_t)((lch ^ (lrow & 7)) << 4);

    auto load_stage = [&](int s, int kt) {
        uint32_t adst = smem_base + (uint32_t)s * GSTG;
        uint32_t bdst = smem_base + 2 * GSTG + (uint32_t)s * GSTG;
        const __nv_bfloat16* asrc = abase + (size_t)kt * 64;
        const __nv_bfloat16* bsrc = bbase + (size_t)kt * 64;
        #pragma unroll
        for (int u = 0; u < 4; u++) {
            int row = lrow + u * 32;
            uint32_t d = (uint32_t)row * 128 + ((uint32_t)(lch ^ (row & 7)) << 4);
            cp16(adst + d, asrc + (size_t)row * K + lch * 8);
            cp16(bdst + d, bsrc + (size_t)row * K + lch * 8);
        }
        asm volatile("cp.async.commit_group;\n");
    };
    (void)sw_off;

    load_stage(0, 0);
    asm volatile("cp.async.wait_group 0;\n" ::: "memory");
    __syncthreads();

    int nt = K / 64;
    for (int t = 0; t < nt; t++) {
        int s = t & 1;
        bool more = (t + 1 < nt);
        if (more) load_stage(s ^ 1, t + 1);

        uint32_t abase_s = smem_base + (uint32_t)s * GSTG;
        uint32_t bbase_s = smem_base + 2 * GSTG + (uint32_t)s * GSTG;

        #pragma unroll
        for (int ks = 0; ks < 4; ks++) {
            int k8 = ks * 2;                       // 16B-chunk base of this k16 step
            uint32_t af[4][4];
            #pragma unroll
            for (int i = 0; i < 4; i++) {
                int row = wm + i * 16 + (lane & 15);
                uint32_t ch = (uint32_t)((k8 + (lane >> 4)) ^ (row & 7));
                ldmx4(af[i], abase_s + (uint32_t)row * 128 + (ch << 4));
            }
            uint32_t b0[4], b1[4];
            {
                int rowb = wn + lane;
                uint32_t c0 = (uint32_t)((k8    ) ^ (rowb & 7));
                uint32_t c1 = (uint32_t)((k8 + 1) ^ (rowb & 7));
                ldmx4(b0, bbase_s + (uint32_t)rowb * 128 + (c0 << 4));
                ldmx4(b1, bbase_s + (uint32_t)rowb * 128 + (c1 << 4));
            }
            #pragma unroll
            for (int i = 0; i < 4; i++)
                #pragma unroll
                for (int j = 0; j < 4; j++)
                    mma_bf16(acc[i][j], af[i][0], af[i][1], af[i][2], af[i][3],
                             b0[j], b1[j]);
        }

        if (more) {
            asm volatile("cp.async.wait_group 0;\n" ::: "memory");
            __syncthreads();
        }
    }

    // ---- epilogue: acc (i,j) -> rows (gid, gid+8), cols (2tig, 2tig+1) ----
    #pragma unroll
    for (int i = 0; i < 4; i++) {
        int r0 = bm + wm + i * 16 + gid;
        #pragma unroll
        for (int j = 0; j < 4; j++) {
            int c0 = bn + wn + j * 8 + tig * 2;
            float v0 = acc[i][j][0], v1 = acc[i][j][1];
            float v2 = acc[i][j][2], v3 = acc[i][j][3];
            if (residual) {
                const float* rr0 = residual + (size_t)r0 * N + c0;
                const float* rr1 = residual + (size_t)(r0 + 8) * N + c0;
                v0 += rr0[0]; v1 += rr0[1]; v2 += rr1[0]; v3 += rr1[1];
            }
            float2 q0 = { v0, v1 }, q1 = { v2, v3 };
            *(float2*)(C + (size_t)r0 * N + c0)       = q0;
            *(float2*)(C + (size_t)(r0 + 8) * N + c0) = q1;
        }
    }
}

// ---------------- weight transpose + bf16 convert: Wt[n][k] = W[k][n] --------
__global__ void wtrans_kernel(const float* __restrict__ W,
                              __nv_bfloat16* __restrict__ Wt, int K, int N) {
    __shared__ float tile[32][33];
    int bx = blockIdx.x * 32;   // n
    int by = blockIdx.y * 32;   // k
    int tx = threadIdx.x & 31, ty = threadIdx.x >> 5;
    #pragma unroll
    for (int r = 0; r < 32; r += 8)
        tile[ty + r][tx] = W[(size_t)(by + ty + r) * N + bx + tx];
    __syncthreads();
    #pragma unroll
    for (int r = 0; r < 32; r += 8)
        Wt[(size_t)(bx + ty + r) * K + by + tx] = __float2bfloat16(tile[tx][ty + r]);
}

// ---------------- RMSNorm (bf16 out) ----------------
__global__ void rmsnorm_kernel(const float* __restrict__ x0,
                               const float* __restrict__ w) {
    int t = blockIdx.x;
    const float* xr = x0 + (size_t)t * DMODEL;
    float s = 0.f;
    #pragma unroll
    for (int i = 0; i < DMODEL / 256; i++) {
        float v = xr[threadIdx.x + i * 256];
        s += v * v;
    }
    #pragma unroll
    for (int o = 16; o > 0; o >>= 1) s += __shfl_xor_sync(0xffffffffu, s, o);
    __shared__ float ws[8];
    if ((threadIdx.x & 31) == 0) ws[threadIdx.x >> 5] = s;
    __syncthreads();
    if (threadIdx.x < 8) {
        float v = ws[threadIdx.x];
        #pragma unroll
        for (int o = 4; o > 0; o >>= 1) v += __shfl_xor_sync(0xffu, v, o);
        if (threadIdx.x == 0) ws[0] = v;
    }
    __syncthreads();
    float rs = rsqrtf(ws[0] / (float)DMODEL + EPS);
    __nv_bfloat16* hr = g_hb + (size_t)t * DMODEL;
    #pragma unroll
    for (int i = 0; i < DMODEL / 256; i++) {
        int c = threadIdx.x + i * 256;
        hr[c] = __float2bfloat16(xr[c] * rs * w[c]);
    }
}

// ---------------- causal depthwise conv (K=4) + SiLU, 4 outputs/thread ------
__global__ void conv_silu_kernel(const float* __restrict__ conv_w,
                                 const float* __restrict__ conv_b) {
    int gidx = blockIdx.x * blockDim.x + threadIdx.x;
    int d  = gidx & (DINNER - 1);
    int q  = gidx >> 11;
    int l4 = q & (LSEQ / 4 - 1);
    int b  = q >> 8;
    int l0 = l4 * 4;

    float w0 = conv_w[d * KCONV + 0];
    float w1 = conv_w[d * KCONV + 1];
    float w2 = conv_w[d * KCONV + 2];
    float w3 = conv_w[d * KCONV + 3];
    float cb = conv_b[d];

    const size_t S = 2 * DINNER;
    const float* base = g_xres + (size_t)(b * LSEQ) * S + d;

    float h0 = 0.f, h1 = 0.f, h2 = 0.f;
    if (l0 > 0) {
        h0 = base[(size_t)(l0 - 3) * S];
        h1 = base[(size_t)(l0 - 2) * S];
        h2 = base[(size_t)(l0 - 1) * S];
    }
    float c0 = base[(size_t)(l0 + 0) * S];
    float c1 = base[(size_t)(l0 + 1) * S];
    float c2 = base[(size_t)(l0 + 2) * S];
    float c3 = base[(size_t)(l0 + 3) * S];

    float o0 = fmaf(w0,h0, fmaf(w1,h1, fmaf(w2,h2, fmaf(w3,c0, cb))));
    float o1 = fmaf(w0,h1, fmaf(w1,h2, fmaf(w2,c0, fmaf(w3,c1, cb))));
    float o2 = fmaf(w0,h2, fmaf(w1,c0, fmaf(w2,c1, fmaf(w3,c2, cb))));
    float o3 = fmaf(w0,c0, fmaf(w1,c1, fmaf(w2,c2, fmaf(w3,c3, cb))));

    size_t t0 = (size_t)(b * LSEQ + l0) * DINNER + d;
    g_xc[t0]              = silu_f(o0);
    g_xc[t0 + DINNER]     = silu_f(o1);
    g_xc[t0 + 2 * DINNER] = silu_f(o2);
    g_xc[t0 + 3 * DINNER] = silu_f(o3);
}

// ---------------- x_proj split-K (16 splits) ----------------
__global__ void xproj_kernel(const float* __restrict__ Wx) {
    __shared__ float sA[32][68];
    __shared__ float sW[32][104];

    int tid = threadIdx.x;
    int bm = blockIdx.x * 64;
    int ks = blockIdx.y;
    int tm = tid & 15;
    int tn = tid >> 4;

    float acc[4][6];
    #pragma unroll
    for (int i = 0; i < 4; i++)
        #pragma unroll
        for (int j = 0; j < 6; j++) acc[i][j] = 0.f;

    int lr = tid >> 2;
    int lc = (tid & 3) * 8;

    for (int k0 = ks * 128; k0 < ks * 128 + 128; k0 += 32) {
        {
            const float* src = g_xc + (size_t)(bm + lr) * DINNER + k0 + lc;
            float4 v0 = *(const float4*)src;
            float4 v1 = *(const float4*)(src + 4);
            sA[lc+0][lr]=v0.x; sA[lc+1][lr]=v0.y; sA[lc+2][lr]=v0.z; sA[lc+3][lr]=v0.w;
            sA[lc+4][lr]=v1.x; sA[lc+5][lr]=v1.y; sA[lc+6][lr]=v1.z; sA[lc+7][lr]=v1.w;
        }
        #pragma unroll
        for (int q = 0; q < 3; q++) {
            int p = tid + 256 * q;
            int row = p / 24, c4 = p % 24;
            float4 v = *(const float4*)(Wx + (size_t)(k0 + row) * XDBL_N + c4 * 4);
            *(float4*)&sW[row][c4 * 4] = v;
        }
        __syncthreads();
        #pragma unroll 8
        for (int k = 0; k < 32; k++) {
            float4 av = *(const float4*)&sA[k][tm * 4];
            float a[4] = { av.x, av.y, av.z, av.w };
            float2 b0 = *(const float2*)&sW[k][tn * 6];
            float2 b1 = *(const float2*)&sW[k][tn * 6 + 2];
            float2 b2 = *(const float2*)&sW[k][tn * 6 + 4];
            float bv[6] = { b0.x, b0.y, b1.x, b1.y, b2.x, b2.y };
            #pragma unroll
            for (int i = 0; i < 4; i++)
                #pragma unroll
                for (int j = 0; j < 6; j++)
                    acc[i][j] = fmaf(a[i], bv[j], acc[i][j]);
        }
        __syncthreads();
    }
    float* dst = g_xp + (size_t)ks * TOK * XDBL_N;
    #pragma unroll
    for (int i = 0; i < 4; i++)
        #pragma unroll
        for (int j = 0; j < 6; j++)
            dst[(size_t)(bm + tm * 4 + i) * XDBL_N + tn * 6 + j] = acc[i][j];
}

__global__ void xproj_reduce() {
    int idx = blockIdx.x * blockDim.x + threadIdx.x;
    if (idx >= TOK * XDBL_N) return;
    float s = 0.f;
    #pragma unroll
    for (int q = 0; q < NSPLIT; q++)
        s += g_xp[(size_t)q * TOK * XDBL_N + idx];
    g_xdbl[idx] = s;
}

// ---------------- delta = softplus(dlt @ W_dt + b_dt), 8 tokens/block --------
__global__ void delta_kernel(const float* __restrict__ W_dt,
                             const float* __restrict__ b_dt) {
    __shared__ float sd[8][DTRANK];
    int tid = threadIdx.x;
    int t0 = blockIdx.x * 8;
    #pragma unroll
    for (int q = 0; q < 2; q++) {
        int p = tid + 256 * q;
        int tok = p >> 6, k = p & 63;
        sd[tok][k] = g_xdbl[(size_t)(t0 + tok) * XDBL_N + k];
    }
    __syncthreads();

    float bb[8];
    #pragma unroll
    for (int j = 0; j < 8; j++) bb[j] = b_dt[tid + 256 * j];
    float acc[8][8];
    #pragma unroll
    for (int tok = 0; tok < 8; tok++)
        #pragma unroll
        for (int j = 0; j < 8; j++) acc[tok][j] = bb[j];

    #pragma unroll 4
    for (int k = 0; k < DTRANK; k++) {
        float w[8];
        #pragma unroll
        for (int j = 0; j < 8; j++) w[j] = W_dt[(size_t)k * DINNER + tid + 256 * j];
        #pragma unroll
        for (int tok = 0; tok < 8; tok++) {
            float dl = sd[tok][k];
            #pragma unroll
            for (int j = 0; j < 8; j++) acc[tok][j] = fmaf(dl, w[j], acc[tok][j]);
        }
    }
    #pragma unroll
    for (int tok = 0; tok < 8; tok++)
        #pragma unroll
        for (int j = 0; j < 8; j++) {
            float x = acc[tok][j];
            float sp = (x > 20.f) ? x : log1pf(__expf(x));
            g_delta[(size_t)(t0 + tok) * DINNER + tid + 256 * j] = sp;
        }
}

// ---------------- scan pass A ----------------
__global__ void scanA_kernel(const float* __restrict__ A) {
    int g = blockIdx.x * blockDim.x + threadIdx.x;
    int d  = g & (DINNER - 1);
    int bc = g >> 11;
    int c  = bc & (NCHUNK - 1);
    int b  = bc >> 5;

    float a[DSTATE], s[DSTATE], P[DSTATE];
    #pragma unroll
    for (int q = 0; q < 4; q++) {
        float4 v = *(const float4*)(A + d * DSTATE + q * 4);
        a[q*4+0]=v.x; a[q*4+1]=v.y; a[q*4+2]=v.z; a[q*4+3]=v.w;
    }
    #pragma unroll
    for (int n = 0; n < DSTATE; n++) { s[n] = 0.f; P[n] = 1.f; }

    int t0 = b * LSEQ + c * CLEN;
    for (int l = 0; l < CLEN; l++) {
        int t = t0 + l;
        float delta = g_delta[(size_t)t * DINNER + d];
        float xv    = g_xc   [(size_t)t * DINNER + d];
        float du    = delta * xv;
        const float* Bv = g_xdbl + (size_t)t * XDBL_N + DTRANK;
        #pragma unroll
        for (int n = 0; n < DSTATE; n++) {
            float dA = __expf(delta * a[n]);
            s[n] = fmaf(dA, s[n], du * Bv[n]);
            P[n] *= dA;
        }
    }
    float* Sp = g_S + (size_t)bc * DN + d * DSTATE;
    float* Pp = g_P + (size_t)bc * DN + d * DSTATE;
    #pragma unroll
    for (int q = 0; q < 4; q++) {
        float4 vs = { s[q*4+0], s[q*4+1], s[q*4+2], s[q*4+3] };
        float4 vp = { P[q*4+0], P[q*4+1], P[q*4+2], P[q*4+3] };
        *(float4*)(Sp + q * 4) = vs;
        *(float4*)(Pp + q * 4) = vp;
    }
}

// ---------------- scan pass B ----------------
__global__ void scanB_kernel() {
    int g = blockIdx.x * blockDim.x + threadIdx.x;
    int idx = g & (DN - 1);
    int b   = g >> 15;
    size_t base = (size_t)b * NCHUNK * DN;
    float s = 0.f;
    for (int c = 0; c < NCHUNK; c++) {
        size_t o = base + (size_t)c * DN + idx;
        g_SI[o] = s;
        s = g_S[o] + g_P[o] * s;
    }
}

// ---------------- scan pass C (bf16 gated output) ----------------
__global__ void scanC_kernel(const float* __restrict__ A,
                             const float* __restrict__ Dp) {
    int g = blockIdx.x * blockDim.x + threadIdx.x;
    int d  = g & (DINNER - 1);
    int bc = g >> 11;
    int c  = bc & (NCHUNK - 1);
    int b  = bc >> 5;

    float a[DSTATE], s[DSTATE];
    #pragma unroll
    for (int q = 0; q < 4; q++) {
        float4 v = *(const float4*)(A + d * DSTATE + q * 4);
        a[q*4+0]=v.x; a[q*4+1]=v.y; a[q*4+2]=v.z; a[q*4+3]=v.w;
        float4 vi = *(const float4*)(g_SI + (size_t)bc * DN + d * DSTATE + q * 4);
        s[q*4+0]=vi.x; s[q*4+1]=vi.y; s[q*4+2]=vi.z; s[q*4+3]=vi.w;
    }
    float Dd = Dp[d];

    int t0 = b * LSEQ + c * CLEN;
    for (int l = 0; l < CLEN; l++) {
        int t = t0 + l;
        float delta = g_delta[(size_t)t * DINNER + d];
        float xv    = g_xc   [(size_t)t * DINNER + d];
        float du    = delta * xv;
        const float* Bv = g_xdbl + (size_t)t * XDBL_N + DTRANK;
        const float* Cv = Bv + DSTATE;
        float y = 0.f;
        #pragma unroll
        for (int n = 0; n < DSTATE; n++) {
            float dA = __expf(delta * a[n]);
            s[n] = fmaf(dA, s[n], du * Bv[n]);
            y = fmaf(s[n], Cv[n], y);
        }
        float res = g_xres[(size_t)t * (2 * DINNER) + DINNER + d];
        g_yb[(size_t)t * DINNER + d] =
            __float2bfloat16((y + xv * Dd) * silu_f(res));
    }
}

// ---------------- launch ----------------
extern "C" void kernel_launch(void* const* d_in, const int* in_sizes, int n_in,
                              void* d_out, int out_size) {
    const float* x0     = (const float*)d_in[0];
    const float* norm_w = (const float*)d_in[1];
    const float* W_in   = (const float*)d_in[2];
    const float* conv_w = (const float*)d_in[3];
    const float* conv_b = (const float*)d_in[4];
    const float* W_x    = (const float*)d_in[5];
    const float* W_dt   = (const float*)d_in[6];
    const float* b_dt   = (const float*)d_in[7];
    const float* Amat   = (const float*)d_in[8];
    const float* Dvec   = (const float*)d_in[9];
    const float* W_out  = (const float*)d_in[10];
    float* out = (float*)d_out;

    __nv_bfloat16 *p_hb, *p_yb, *p_wint, *p_woutt;
    float *p_xres;
    cudaGetSymbolAddress((void**)&p_hb,    g_hb);
    cudaGetSymbolAddress((void**)&p_yb,    g_yb);
    cudaGetSymbolAddress((void**)&p_wint,  g_wint);
    cudaGetSymbolAddress((void**)&p_woutt, g_woutt);
    cudaGetSymbolAddress((void**)&p_xres,  g_xres);

    cudaFuncSetAttribute(gemm_bf16, cudaFuncAttributeMaxDynamicSharedMemorySize,
                         GEMM_SMEM);

    // weight transposes (bf16)
    wtrans_kernel<<<dim3((2 * DINNER) / 32, DMODEL / 32), 256>>>(
        W_in, p_wint, DMODEL, 2 * DINNER);
    wtrans_kernel<<<dim3(DMODEL / 32, DINNER / 32), 256>>>(
        W_out, p_woutt, DINNER, DMODEL);

    // 1) RMSNorm -> bf16
    rmsnorm_kernel<<<TOK, 256>>>(x0, norm_w);

    // 2) in_proj (bf16 mma): [2048,1024] @ [1024,4096]
    gemm_bf16<<<dim3((2 * DINNER) / 128, TOK / 128), 256, GEMM_SMEM>>>(
        p_hb, p_wint, p_xres, TOK, 2 * DINNER, DMODEL, nullptr);

    // 3) conv + silu
    conv_silu_kernel<<<(TOK / 4 * DINNER) / 256, 256>>>(conv_w, conv_b);

    // 4) x_proj split-K + reduce
    xproj_kernel<<<dim3(TOK / 64, NSPLIT), 256>>>(W_x);
    xproj_reduce<<<(TOK * XDBL_N) / 256, 256>>>();

    // 5) delta
    delta_kernel<<<TOK / 8, 256>>>(W_dt, b_dt);

    // 6) chunked selective scan
    scanA_kernel<<<(BATCH * NCHUNK * DINNER) / 256, 256>>>(Amat);
    scanB_kernel<<<(BATCH * DN) / 256, 256>>>();
    scanC_kernel<<<(BATCH * NCHUNK * DINNER) / 256, 256>>>(Amat, Dvec);

    // 7) out_proj (bf16 mma) + residual: [2048,2048] @ [2048,1024]
    gemm_bf16<<<dim3(DMODEL / 128, TOK / 128), 256, GEMM_SMEM>>>(
        p_yb, p_woutt, out, TOK, DMODEL, DINNER, x0);
}

// round 6
// speedup vs baseline: 7.9867x; 1.0728x over previous
#include <cuda_runtime.h>
#include <cuda_bf16.h>
#include <math.h>
#include <stdint.h>

// ---------------- problem constants ----------------
#define BATCH   2
#define LSEQ    1024
#define DMODEL  1024
#define DINNER  2048
#define DSTATE  16
#define DTRANK  64
#define KCONV   4
#define TOK     (BATCH*LSEQ)        // 2048 tokens
#define XDBL_N  (DTRANK + 2*DSTATE) // 96
#define EPS     1e-5f

#define NCHUNK  32
#define CLEN    (LSEQ/NCHUNK)       // 32
#define DN      (DINNER*DSTATE)     // 32768
#define NSPLIT  16

// ---------------- scratch ----------------
__device__ __align__(16) __nv_bfloat16 g_hb    [TOK * DMODEL];       // rmsnorm out
__device__ __align__(16) __nv_bfloat16 g_yb    [TOK * DINNER];       // scan out
__device__ __align__(16) __nv_bfloat16 g_wint  [2*DINNER * DMODEL];  // W_in^T
__device__ __align__(16) __nv_bfloat16 g_woutt [DMODEL * DINNER];    // W_out^T
__device__ __align__(16) __nv_bfloat16 g_xresb [TOK * 2 * DINNER];   // in_proj out (x|res)
__device__ __align__(16) __nv_bfloat16 g_xcb   [TOK * DINNER];       // conv+silu out
__device__ __align__(16) __nv_bfloat16 g_deltab[TOK * DINNER];       // softplus(dt)
__device__ __align__(16) float g_xdbl [TOK * XDBL_N];
__device__ __align__(16) float g_xp   [NSPLIT * TOK * XDBL_N];
__device__ __align__(16) float g_S    [BATCH * NCHUNK * DN];
__device__ __align__(16) float g_P    [BATCH * NCHUNK * DN];
__device__ __align__(16) float g_SI   [BATCH * NCHUNK * DN];

// ---------------- helpers ----------------
__device__ __forceinline__ float silu_f(float x) {
    return x / (1.f + __expf(-x));
}
__device__ __forceinline__ void cp16(uint32_t smem, const void* g) {
    asm volatile("cp.async.cg.shared.global [%0], [%1], 16;\n" :: "r"(smem), "l"(g));
}
__device__ __forceinline__ void mma_bf16(float c[4],
    uint32_t a0, uint32_t a1, uint32_t a2, uint32_t a3,
    uint32_t b0, uint32_t b1) {
    asm volatile(
        "mma.sync.aligned.m16n8k16.row.col.f32.bf16.bf16.f32 "
        "{%0,%1,%2,%3}, {%4,%5,%6,%7}, {%8,%9}, {%0,%1,%2,%3};"
        : "+f"(c[0]), "+f"(c[1]), "+f"(c[2]), "+f"(c[3])
        : "r"(a0), "r"(a1), "r"(a2), "r"(a3), "r"(b0), "r"(b1));
}
__device__ __forceinline__ void ldmx4(uint32_t r[4], uint32_t addr) {
    asm volatile(
        "ldmatrix.sync.aligned.m8n8.x4.shared.b16 {%0,%1,%2,%3}, [%4];"
        : "=r"(r[0]), "=r"(r[1]), "=r"(r[2]), "=r"(r[3]) : "r"(addr));
}

// ---------------- bf16 MMA GEMM, 3-stage pipeline ----------------
// C[M,N] = A[M,K](bf16) @ Bt[N,K](bf16)^T (+residual), OutT out.
// CTA 128x128, BK=64, 256 threads (8 warps 2x4), warp tile 64x32.
#define GSTG   16384u
#define NSTAGE 3
#define GEMM_SMEM (2 * NSTAGE * GSTG)     // 96 KB

template <typename OutT>
__global__ void __launch_bounds__(256)
gemm_bf16(const __nv_bfloat16* __restrict__ A, const __nv_bfloat16* __restrict__ Bt,
          OutT* __restrict__ C, int M, int N, int K,
          const float* __restrict__ residual) {
    extern __shared__ char smem[];
    uint32_t smem_base;
    asm("{ .reg .u64 t; cvta.to.shared.u64 t, %1; cvt.u32.u64 %0, t; }"
        : "=r"(smem_base) : "l"(smem));

    int tid  = threadIdx.x;
    int lane = tid & 31, wid = tid >> 5;
    int bm = blockIdx.y * 128, bn = blockIdx.x * 128;
    int wm = (wid >> 2) * 64, wn = (wid & 3) * 32;
    int gid = lane >> 2, tig = lane & 3;

    float acc[4][4][4];
    #pragma unroll
    for (int i = 0; i < 4; i++)
        #pragma unroll
        for (int j = 0; j < 4; j++)
            #pragma unroll
            for (int q = 0; q < 4; q++) acc[i][j][q] = 0.f;

    const __nv_bfloat16* abase = A + (size_t)bm * K;
    const __nv_bfloat16* bbase = Bt + (size_t)bn * K;

    int lrow = tid >> 3;            // base row 0..31 (advance by 32)
    int lch  = tid & 7;             // 16B chunk 0..7 within row

    auto load_stage = [&](int s, int kt) {
        uint32_t adst = smem_base + (uint32_t)s * GSTG;
        uint32_t bdst = smem_base + NSTAGE * GSTG + (uint32_t)s * GSTG;
        const __nv_bfloat16* asrc = abase + (size_t)kt * 64;
        const __nv_bfloat16* bsrc = bbase + (size_t)kt * 64;
        #pragma unroll
        for (int u = 0; u < 4; u++) {
            int row = lrow + u * 32;
            uint32_t d = (uint32_t)row * 128 + ((uint32_t)(lch ^ (row & 7)) << 4);
            cp16(adst + d, asrc + (size_t)row * K + lch * 8);
            cp16(bdst + d, bsrc + (size_t)row * K + lch * 8);
        }
        asm volatile("cp.async.commit_group;\n");
    };

    int nt = K / 64;                // >= 16 for all calls here
    load_stage(0, 0);
    load_stage(1, 1);

    for (int t = 0; t < nt; t++) {
        int s = t % NSTAGE;
        if (t + 1 < nt) asm volatile("cp.async.wait_group 1;\n" ::: "memory");
        else            asm volatile("cp.async.wait_group 0;\n" ::: "memory");
        __syncthreads();
        if (t + 2 < nt) load_stage((t + 2) % NSTAGE, t + 2);

        uint32_t abase_s = smem_base + (uint32_t)s * GSTG;
        uint32_t bbase_s = smem_base + NSTAGE * GSTG + (uint32_t)s * GSTG;

        #pragma unroll
        for (int ks = 0; ks < 4; ks++) {
            int k8 = ks * 2;
            uint32_t af[4][4];
            #pragma unroll
            for (int i = 0; i < 4; i++) {
                int row = wm + i * 16 + (lane & 15);
                uint32_t ch = (uint32_t)((k8 + (lane >> 4)) ^ (row & 7));
                ldmx4(af[i], abase_s + (uint32_t)row * 128 + (ch << 4));
            }
            uint32_t b0[4], b1[4];
            {
                int rowb = wn + lane;
                uint32_t c0 = (uint32_t)((k8    ) ^ (rowb & 7));
                uint32_t c1 = (uint32_t)((k8 + 1) ^ (rowb & 7));
                ldmx4(b0, bbase_s + (uint32_t)rowb * 128 + (c0 << 4));
                ldmx4(b1, bbase_s + (uint32_t)rowb * 128 + (c1 << 4));
            }
            #pragma unroll
            for (int i = 0; i < 4; i++)
                #pragma unroll
                for (int j = 0; j < 4; j++)
                    mma_bf16(acc[i][j], af[i][0], af[i][1], af[i][2], af[i][3],
                             b0[j], b1[j]);
        }
        __syncthreads();    // all warps done with stage s before refill next iter
    }

    // ---- epilogue ----
    #pragma unroll
    for (int i = 0; i < 4; i++) {
        int r0 = bm + wm + i * 16 + gid;
        #pragma unroll
        for (int j = 0; j < 4; j++) {
            int c0 = bn + wn + j * 8 + tig * 2;
            float v0 = acc[i][j][0], v1 = acc[i][j][1];
            float v2 = acc[i][j][2], v3 = acc[i][j][3];
            if (residual) {
                const float* rr0 = residual + (size_t)r0 * N + c0;
                const float* rr1 = residual + (size_t)(r0 + 8) * N + c0;
                v0 += rr0[0]; v1 += rr0[1]; v2 += rr1[0]; v3 += rr1[1];
            }
            if constexpr (sizeof(OutT) == 2) {
                __nv_bfloat162 p0 = { __float2bfloat16(v0), __float2bfloat16(v1) };
                __nv_bfloat162 p1 = { __float2bfloat16(v2), __float2bfloat16(v3) };
                *(__nv_bfloat162*)((__nv_bfloat16*)C + (size_t)r0 * N + c0)       = p0;
                *(__nv_bfloat162*)((__nv_bfloat16*)C + (size_t)(r0 + 8) * N + c0) = p1;
            } else {
                float2 q0 = { v0, v1 }, q1 = { v2, v3 };
                *(float2*)((float*)C + (size_t)r0 * N + c0)       = q0;
                *(float2*)((float*)C + (size_t)(r0 + 8) * N + c0) = q1;
            }
        }
    }
}

// ---------------- weight transpose + bf16 convert ----------------
__global__ void wtrans_kernel(const float* __restrict__ W,
                              __nv_bfloat16* __restrict__ Wt, int K, int N) {
    __shared__ float tile[32][33];
    int bx = blockIdx.x * 32;   // n
    int by = blockIdx.y * 32;   // k
    int tx = threadIdx.x & 31, ty = threadIdx.x >> 5;
    #pragma unroll
    for (int r = 0; r < 32; r += 8)
        tile[ty + r][tx] = W[(size_t)(by + ty + r) * N + bx + tx];
    __syncthreads();
    #pragma unroll
    for (int r = 0; r < 32; r += 8)
        Wt[(size_t)(bx + ty + r) * K + by + tx] = __float2bfloat16(tile[tx][ty + r]);
}

// ---------------- RMSNorm (bf16 out) ----------------
__global__ void rmsnorm_kernel(const float* __restrict__ x0,
                               const float* __restrict__ w) {
    int t = blockIdx.x;
    const float* xr = x0 + (size_t)t * DMODEL;
    float s = 0.f;
    #pragma unroll
    for (int i = 0; i < DMODEL / 256; i++) {
        float v = xr[threadIdx.x + i * 256];
        s += v * v;
    }
    #pragma unroll
    for (int o = 16; o > 0; o >>= 1) s += __shfl_xor_sync(0xffffffffu, s, o);
    __shared__ float ws[8];
    if ((threadIdx.x & 31) == 0) ws[threadIdx.x >> 5] = s;
    __syncthreads();
    if (threadIdx.x < 8) {
        float v = ws[threadIdx.x];
        #pragma unroll
        for (int o = 4; o > 0; o >>= 1) v += __shfl_xor_sync(0xffu, v, o);
        if (threadIdx.x == 0) ws[0] = v;
    }
    __syncthreads();
    float rs = rsqrtf(ws[0] / (float)DMODEL + EPS);
    __nv_bfloat16* hr = g_hb + (size_t)t * DMODEL;
    #pragma unroll
    for (int i = 0; i < DMODEL / 256; i++) {
        int c = threadIdx.x + i * 256;
        hr[c] = __float2bfloat16(xr[c] * rs * w[c]);
    }
}

// ---------------- causal depthwise conv (K=4) + SiLU, 4 outputs/thread ------
__global__ void conv_silu_kernel(const float* __restrict__ conv_w,
                                 const float* __restrict__ conv_b) {
    int gidx = blockIdx.x * blockDim.x + threadIdx.x;
    int d  = gidx & (DINNER - 1);
    int q  = gidx >> 11;
    int l4 = q & (LSEQ / 4 - 1);
    int b  = q >> 8;
    int l0 = l4 * 4;

    float w0 = conv_w[d * KCONV + 0];
    float w1 = conv_w[d * KCONV + 1];
    float w2 = conv_w[d * KCONV + 2];
    float w3 = conv_w[d * KCONV + 3];
    float cb = conv_b[d];

    const size_t S = 2 * DINNER;
    const __nv_bfloat16* base = g_xresb + (size_t)(b * LSEQ) * S + d;

    float h0 = 0.f, h1 = 0.f, h2 = 0.f;
    if (l0 > 0) {
        h0 = __bfloat162float(base[(size_t)(l0 - 3) * S]);
        h1 = __bfloat162float(base[(size_t)(l0 - 2) * S]);
        h2 = __bfloat162float(base[(size_t)(l0 - 1) * S]);
    }
    float c0 = __bfloat162float(base[(size_t)(l0 + 0) * S]);
    float c1 = __bfloat162float(base[(size_t)(l0 + 1) * S]);
    float c2 = __bfloat162float(base[(size_t)(l0 + 2) * S]);
    float c3 = __bfloat162float(base[(size_t)(l0 + 3) * S]);

    float o0 = fmaf(w0,h0, fmaf(w1,h1, fmaf(w2,h2, fmaf(w3,c0, cb))));
    float o1 = fmaf(w0,h1, fmaf(w1,h2, fmaf(w2,c0, fmaf(w3,c1, cb))));
    float o2 = fmaf(w0,h2, fmaf(w1,c0, fmaf(w2,c1, fmaf(w3,c2, cb))));
    float o3 = fmaf(w0,c0, fmaf(w1,c1, fmaf(w2,c2, fmaf(w3,c3, cb))));

    size_t t0 = (size_t)(b * LSEQ + l0) * DINNER + d;
    g_xcb[t0]              = __float2bfloat16(silu_f(o0));
    g_xcb[t0 + DINNER]     = __float2bfloat16(silu_f(o1));
    g_xcb[t0 + 2 * DINNER] = __float2bfloat16(silu_f(o2));
    g_xcb[t0 + 3 * DINNER] = __float2bfloat16(silu_f(o3));
}

// ---------------- x_proj split-K (16 splits), bf16 A ----------------
__global__ void xproj_kernel(const float* __restrict__ Wx) {
    __shared__ float sA[32][68];
    __shared__ float sW[32][104];

    int tid = threadIdx.x;
    int bm = blockIdx.x * 64;
    int ks = blockIdx.y;
    int tm = tid & 15;
    int tn = tid >> 4;

    float acc[4][6];
    #pragma unroll
    for (int i = 0; i < 4; i++)
        #pragma unroll
        for (int j = 0; j < 6; j++) acc[i][j] = 0.f;

    int lr = tid >> 2;
    int lc = (tid & 3) * 8;

    for (int k0 = ks * 128; k0 < ks * 128 + 128; k0 += 32) {
        {
            const __nv_bfloat16* src = g_xcb + (size_t)(bm + lr) * DINNER + k0 + lc;
            __nv_bfloat162 v[4];
            *(uint4*)v = *(const uint4*)src;      // 8 bf16
            #pragma unroll
            for (int e = 0; e < 4; e++) {
                sA[lc + 2*e    ][lr] = __bfloat162float(v[e].x);
                sA[lc + 2*e + 1][lr] = __bfloat162float(v[e].y);
            }
        }
        #pragma unroll
        for (int q = 0; q < 3; q++) {
            int p = tid + 256 * q;
            int row = p / 24, c4 = p % 24;
            float4 v = *(const float4*)(Wx + (size_t)(k0 + row) * XDBL_N + c4 * 4);
            *(float4*)&sW[row][c4 * 4] = v;
        }
        __syncthreads();
        #pragma unroll 8
        for (int k = 0; k < 32; k++) {
            float4 av = *(const float4*)&sA[k][tm * 4];
            float a[4] = { av.x, av.y, av.z, av.w };
            float2 b0 = *(const float2*)&sW[k][tn * 6];
            float2 b1 = *(const float2*)&sW[k][tn * 6 + 2];
            float2 b2 = *(const float2*)&sW[k][tn * 6 + 4];
            float bv[6] = { b0.x, b0.y, b1.x, b1.y, b2.x, b2.y };
            #pragma unroll
            for (int i = 0; i < 4; i++)
                #pragma unroll
                for (int j = 0; j < 6; j++)
                    acc[i][j] = fmaf(a[i], bv[j], acc[i][j]);
        }
        __syncthreads();
    }
    float* dst = g_xp + (size_t)ks * TOK * XDBL_N;
    #pragma unroll
    for (int i = 0; i < 4; i++)
        #pragma unroll
        for (int j = 0; j < 6; j++)
            dst[(size_t)(bm + tm * 4 + i) * XDBL_N + tn * 6 + j] = acc[i][j];
}

__global__ void xproj_reduce() {
    int idx = blockIdx.x * blockDim.x + threadIdx.x;
    if (idx >= TOK * XDBL_N) return;
    float s = 0.f;
    #pragma unroll
    for (int q = 0; q < NSPLIT; q++)
        s += g_xp[(size_t)q * TOK * XDBL_N + idx];
    g_xdbl[idx] = s;
}

// ---------------- delta: 16 tokens/block, 4 cols/thread, bf16 out ----------
__global__ void delta_kernel(const float* __restrict__ W_dt,
                             const float* __restrict__ b_dt) {
    __shared__ float sd[16][DTRANK];
    int tid = threadIdx.x;
    int t0 = blockIdx.x * 16;
    int cb = blockIdx.y * 1024;          // column base (0 or 1024)
    #pragma unroll
    for (int q = 0; q < 4; q++) {
        int p = tid + 256 * q;
        int tok = p >> 6, k = p & 63;
        sd[tok][k] = g_xdbl[(size_t)(t0 + tok) * XDBL_N + k];
    }
    __syncthreads();

    float bb[4];
    #pragma unroll
    for (int j = 0; j < 4; j++) bb[j] = b_dt[cb + tid + 256 * j];
    float acc[16][4];
    #pragma unroll
    for (int tok = 0; tok < 16; tok++)
        #pragma unroll
        for (int j = 0; j < 4; j++) acc[tok][j] = bb[j];

    #pragma unroll 4
    for (int k = 0; k < DTRANK; k++) {
        float w[4];
        #pragma unroll
        for (int j = 0; j < 4; j++)
            w[j] = W_dt[(size_t)k * DINNER + cb + tid + 256 * j];
        #pragma unroll
        for (int tok = 0; tok < 16; tok++) {
            float dl = sd[tok][k];
            #pragma unroll
            for (int j = 0; j < 4; j++) acc[tok][j] = fmaf(dl, w[j], acc[tok][j]);
        }
    }
    #pragma unroll
    for (int tok = 0; tok < 16; tok++)
        #pragma unroll
        for (int j = 0; j < 4; j++) {
            float x = acc[tok][j];
            float sp = (x > 20.f) ? x : log1pf(__expf(x));
            g_deltab[(size_t)(t0 + tok) * DINNER + cb + tid + 256 * j] =
                __float2bfloat16(sp);
        }
}

// ---------------- scan pass A ----------------
__global__ void scanA_kernel(const float* __restrict__ A) {
    int g = blockIdx.x * blockDim.x + threadIdx.x;
    int d  = g & (DINNER - 1);
    int bc = g >> 11;
    int c  = bc & (NCHUNK - 1);
    int b  = bc >> 5;

    float a[DSTATE], s[DSTATE], P[DSTATE];
    #pragma unroll
    for (int q = 0; q < 4; q++) {
        float4 v = *(const float4*)(A + d * DSTATE + q * 4);
        a[q*4+0]=v.x; a[q*4+1]=v.y; a[q*4+2]=v.z; a[q*4+3]=v.w;
    }
    #pragma unroll
    for (int n = 0; n < DSTATE; n++) { s[n] = 0.f; P[n] = 1.f; }

    int t0 = b * LSEQ + c * CLEN;
    for (int l = 0; l < CLEN; l++) {
        int t = t0 + l;
        float delta = __bfloat162float(g_deltab[(size_t)t * DINNER + d]);
        float xv    = __bfloat162float(g_xcb   [(size_t)t * DINNER + d]);
        float du    = delta * xv;
        const float* Bv = g_xdbl + (size_t)t * XDBL_N + DTRANK;
        #pragma unroll
        for (int n = 0; n < DSTATE; n++) {
            float dA = __expf(delta * a[n]);
            s[n] = fmaf(dA, s[n], du * Bv[n]);
            P[n] *= dA;
        }
    }
    float* Sp = g_S + (size_t)bc * DN + d * DSTATE;
    float* Pp = g_P + (size_t)bc * DN + d * DSTATE;
    #pragma unroll
    for (int q = 0; q < 4; q++) {
        float4 vs = { s[q*4+0], s[q*4+1], s[q*4+2], s[q*4+3] };
        float4 vp = { P[q*4+0], P[q*4+1], P[q*4+2], P[q*4+3] };
        *(float4*)(Sp + q * 4) = vs;
        *(float4*)(Pp + q * 4) = vp;
    }
}

// ---------------- scan pass B ----------------
__global__ void scanB_kernel() {
    int g = blockIdx.x * blockDim.x + threadIdx.x;
    int idx = g & (DN - 1);
    int b   = g >> 15;
    size_t base = (size_t)b * NCHUNK * DN;
    float s = 0.f;
    for (int c = 0; c < NCHUNK; c++) {
        size_t o = base + (size_t)c * DN + idx;
        g_SI[o] = s;
        s = g_S[o] + g_P[o] * s;
    }
}

// ---------------- scan pass C (bf16 gated output) ----------------
__global__ void scanC_kernel(const float* __restrict__ A,
                             const float* __restrict__ Dp) {
    int g = blockIdx.x * blockDim.x + threadIdx.x;
    int d  = g & (DINNER - 1);
    int bc = g >> 11;
    int c  = bc & (NCHUNK - 1);
    int b  = bc >> 5;

    float a[DSTATE], s[DSTATE];
    #pragma unroll
    for (int q = 0; q < 4; q++) {
        float4 v = *(const float4*)(A + d * DSTATE + q * 4);
        a[q*4+0]=v.x; a[q*4+1]=v.y; a[q*4+2]=v.z; a[q*4+3]=v.w;
        float4 vi = *(const float4*)(g_SI + (size_t)bc * DN + d * DSTATE + q * 4);
        s[q*4+0]=vi.x; s[q*4+1]=vi.y; s[q*4+2]=vi.z; s[q*4+3]=vi.w;
    }
    float Dd = Dp[d];

    int t0 = b * LSEQ + c * CLEN;
    for (int l = 0; l < CLEN; l++) {
        int t = t0 + l;
        float delta = __bfloat162float(g_deltab[(size_t)t * DINNER + d]);
        float xv    = __bfloat162float(g_xcb   [(size_t)t * DINNER + d]);
        float du    = delta * xv;
        const float* Bv = g_xdbl + (size_t)t * XDBL_N + DTRANK;
        const float* Cv = Bv + DSTATE;
        float y = 0.f;
        #pragma unroll
        for (int n = 0; n < DSTATE; n++) {
            float dA = __expf(delta * a[n]);
            s[n] = fmaf(dA, s[n], du * Bv[n]);
            y = fmaf(s[n], Cv[n], y);
        }
        float res = __bfloat162float(
            g_xresb[(size_t)t * (2 * DINNER) + DINNER + d]);
        g_yb[(size_t)t * DINNER + d] =
            __float2bfloat16((y + xv * Dd) * silu_f(res));
    }
}

// ---------------- launch ----------------
extern "C" void kernel_launch(void* const* d_in, const int* in_sizes, int n_in,
                              void* d_out, int out_size) {
    const float* x0     = (const float*)d_in[0];
    const float* norm_w = (const float*)d_in[1];
    const float* W_in   = (const float*)d_in[2];
    const float* conv_w = (const float*)d_in[3];
    const float* conv_b = (const float*)d_in[4];
    const float* W_x    = (const float*)d_in[5];
    const float* W_dt   = (const float*)d_in[6];
    const float* b_dt   = (const float*)d_in[7];
    const float* Amat   = (const float*)d_in[8];
    const float* Dvec   = (const float*)d_in[9];
    const float* W_out  = (const float*)d_in[10];
    float* out = (float*)d_out;

    __nv_bfloat16 *p_hb, *p_yb, *p_wint, *p_woutt, *p_xresb;
    cudaGetSymbolAddress((void**)&p_hb,    g_hb);
    cudaGetSymbolAddress((void**)&p_yb,    g_yb);
    cudaGetSymbolAddress((void**)&p_wint,  g_wint);
    cudaGetSymbolAddress((void**)&p_woutt, g_woutt);
    cudaGetSymbolAddress((void**)&p_xresb, g_xresb);

    cudaFuncSetAttribute(gemm_bf16<__nv_bfloat16>,
                         cudaFuncAttributeMaxDynamicSharedMemorySize, GEMM_SMEM);
    cudaFuncSetAttribute(gemm_bf16<float>,
                         cudaFuncAttributeMaxDynamicSharedMemorySize, GEMM_SMEM);

    // weight transposes (bf16)
    wtrans_kernel<<<dim3((2 * DINNER) / 32, DMODEL / 32), 256>>>(
        W_in, p_wint, DMODEL, 2 * DINNER);
    wtrans_kernel<<<dim3(DMODEL / 32, DINNER / 32), 256>>>(
        W_out, p_woutt, DINNER, DMODEL);

    // 1) RMSNorm -> bf16
    rmsnorm_kernel<<<TOK, 256>>>(x0, norm_w);

    // 2) in_proj (bf16 mma, bf16 out): [2048,1024] @ [1024,4096]
    gemm_bf16<__nv_bfloat16><<<dim3((2 * DINNER) / 128, TOK / 128), 256, GEMM_SMEM>>>(
        p_hb, p_wint, p_xresb, TOK, 2 * DINNER, DMODEL, nullptr);

    // 3) conv + silu
    conv_silu_kernel<<<(TOK / 4 * DINNER) / 256, 256>>>(conv_w, conv_b);

    // 4) x_proj split-K + reduce
    xproj_kernel<<<dim3(TOK / 64, NSPLIT), 256>>>(W_x);
    xproj_reduce<<<(TOK * XDBL_N) / 256, 256>>>();

    // 5) delta
    delta_kernel<<<dim3(TOK / 16, 2), 256>>>(W_dt, b_dt);

    // 6) chunked selective scan
    scanA_kernel<<<(BATCH * NCHUNK * DINNER) / 256, 256>>>(Amat);
    scanB_kernel<<<(BATCH * DN) / 256, 256>>>();
    scanC_kernel<<<(BATCH * NCHUNK * DINNER) / 256, 256>>>(Amat, Dvec);

    // 7) out_proj (bf16 mma, fp32 out) + residual: [2048,2048] @ [2048,1024]
    gemm_bf16<float><<<dim3(DMODEL / 128, TOK / 128), 256, GEMM_SMEM>>>(
        p_yb, p_woutt, out, TOK, DMODEL, DINNER, x0);
}

// round 7
// speedup vs baseline: 8.7862x; 1.1001x over previous
#include <cuda_runtime.h>
#include <cuda_bf16.h>
#include <math.h>
#include <stdint.h>

// ---------------- problem constants ----------------
#define BATCH   2
#define LSEQ    1024
#define DMODEL  1024
#define DINNER  2048
#define DSTATE  16
#define DTRANK  64
#define KCONV   4
#define TOK     (BATCH*LSEQ)        // 2048 tokens
#define XDBL_N  96
#define XPAD    128                 // padded xdbl stride
#define EPS     1e-5f

#define NCHUNK  32
#define CLEN    (LSEQ/NCHUNK)       // 32
#define DN      (DINNER*DSTATE)     // 32768
#define XKSPLIT 8                   // x_proj K splits (MMA)

// ---------------- scratch ----------------
__device__ __align__(16) __nv_bfloat16 g_hb    [TOK * DMODEL];       // rmsnorm out
__device__ __align__(16) __nv_bfloat16 g_yb    [TOK * DINNER];       // scan out
__device__ __align__(16) __nv_bfloat16 g_wint  [2*DINNER * DMODEL];  // W_in^T
__device__ __align__(16) __nv_bfloat16 g_woutt [DMODEL * DINNER];    // W_out^T
__device__ __align__(16) __nv_bfloat16 g_wxt   [XPAD * DINNER];      // W_x^T padded
__device__ __align__(16) __nv_bfloat16 g_xresb [TOK * 2 * DINNER];   // in_proj out
__device__ __align__(16) __nv_bfloat16 g_xcb   [TOK * DINNER];       // conv+silu out
__device__ __align__(16) __nv_bfloat16 g_deltab[TOK * DINNER];       // softplus(dt)
__device__ __align__(16) float g_xdbl [TOK * XPAD];                  // x_proj out (padded)
__device__ __align__(16) float g_xpf  [XKSPLIT * TOK * XPAD];        // x_proj partials
__device__ __align__(16) float g_S    [BATCH * NCHUNK * DN];
__device__ __align__(16) float g_P    [BATCH * NCHUNK * DN];
__device__ __align__(16) float g_SI   [BATCH * NCHUNK * DN];

// ---------------- helpers ----------------
__device__ __forceinline__ float silu_f(float x) {
    return x / (1.f + __expf(-x));
}
__device__ __forceinline__ void cp16(uint32_t smem, const void* g) {
    asm volatile("cp.async.cg.shared.global [%0], [%1], 16;\n" :: "r"(smem), "l"(g));
}
__device__ __forceinline__ void mma_bf16(float c[4],
    uint32_t a0, uint32_t a1, uint32_t a2, uint32_t a3,
    uint32_t b0, uint32_t b1) {
    asm volatile(
        "mma.sync.aligned.m16n8k16.row.col.f32.bf16.bf16.f32 "
        "{%0,%1,%2,%3}, {%4,%5,%6,%7}, {%8,%9}, {%0,%1,%2,%3};"
        : "+f"(c[0]), "+f"(c[1]), "+f"(c[2]), "+f"(c[3])
        : "r"(a0), "r"(a1), "r"(a2), "r"(a3), "r"(b0), "r"(b1));
}
__device__ __forceinline__ void ldmx4(uint32_t r[4], uint32_t addr) {
    asm volatile(
        "ldmatrix.sync.aligned.m8n8.x4.shared.b16 {%0,%1,%2,%3}, [%4];"
        : "=r"(r[0]), "=r"(r[1]), "=r"(r[2]), "=r"(r[3]) : "r"(addr));
}

// ---------------- bf16 MMA GEMM, 3-stage pipeline, split-K capable ----------
// Cz[M,N] = A[M,*](bf16, row stride lda) @ Bt[N,*](bf16, row stride ldb)^T
// over K-slice [z*Kslice, (z+1)*Kslice); Cz = C + z*M*N. (+residual), OutT out.
// CTA 128x128, BK=64, 256 threads (8 warps 2x4), warp tile 64x32.
#define GSTG   16384u
#define NSTAGE 3
#define GEMM_SMEM (2 * NSTAGE * GSTG)     // 96 KB

template <typename OutT>
__global__ void __launch_bounds__(256)
gemm_bf16(const __nv_bfloat16* __restrict__ A, const __nv_bfloat16* __restrict__ Bt,
          OutT* __restrict__ C, int M, int N, int lda, int ldb, int Kslice,
          const float* __restrict__ residual) {
    extern __shared__ char smem[];
    uint32_t smem_base;
    asm("{ .reg .u64 t; cvta.to.shared.u64 t, %1; cvt.u32.u64 %0, t; }"
        : "=r"(smem_base) : "l"(smem));

    int tid  = threadIdx.x;
    int lane = tid & 31, wid = tid >> 5;
    int bm = blockIdx.y * 128, bn = blockIdx.x * 128;
    int wm = (wid >> 2) * 64, wn = (wid & 3) * 32;
    int gid = lane >> 2, tig = lane & 3;
    int koff = blockIdx.z * Kslice;

    float acc[4][4][4];
    #pragma unroll
    for (int i = 0; i < 4; i++)
        #pragma unroll
        for (int j = 0; j < 4; j++)
            #pragma unroll
            for (int q = 0; q < 4; q++) acc[i][j][q] = 0.f;

    const __nv_bfloat16* abase = A + (size_t)bm * lda + koff;
    const __nv_bfloat16* bbase = Bt + (size_t)bn * ldb + koff;
    OutT* Cz = C + (size_t)blockIdx.z * M * N;

    int lrow = tid >> 3;            // base row 0..31 (advance by 32)
    int lch  = tid & 7;             // 16B chunk 0..7 within row

    auto load_stage = [&](int s, int kt) {
        uint32_t adst = smem_base + (uint32_t)s * GSTG;
        uint32_t bdst = smem_base + NSTAGE * GSTG + (uint32_t)s * GSTG;
        const __nv_bfloat16* asrc = abase + (size_t)kt * 64;
        const __nv_bfloat16* bsrc = bbase + (size_t)kt * 64;
        #pragma unroll
        for (int u = 0; u < 4; u++) {
            int row = lrow + u * 32;
            uint32_t d = (uint32_t)row * 128 + ((uint32_t)(lch ^ (row & 7)) << 4);
            cp16(adst + d, asrc + (size_t)row * lda + lch * 8);
            cp16(bdst + d, bsrc + (size_t)row * ldb + lch * 8);
        }
        asm volatile("cp.async.commit_group;\n");
    };

    int nt = Kslice / 64;           // >= 2 for all calls here
    load_stage(0, 0);
    load_stage(1, 1);

    for (int t = 0; t < nt; t++) {
        int s = t % NSTAGE;
        if (t + 1 < nt) asm volatile("cp.async.wait_group 1;\n" ::: "memory");
        else            asm volatile("cp.async.wait_group 0;\n" ::: "memory");
        __syncthreads();
        if (t + 2 < nt) load_stage((t + 2) % NSTAGE, t + 2);

        uint32_t abase_s = smem_base + (uint32_t)s * GSTG;
        uint32_t bbase_s = smem_base + NSTAGE * GSTG + (uint32_t)s * GSTG;

        #pragma unroll
        for (int ks = 0; ks < 4; ks++) {
            int k8 = ks * 2;
            uint32_t af[4][4];
            #pragma unroll
            for (int i = 0; i < 4; i++) {
                int row = wm + i * 16 + (lane & 15);
                uint32_t ch = (uint32_t)((k8 + (lane >> 4)) ^ (row & 7));
                ldmx4(af[i], abase_s + (uint32_t)row * 128 + (ch << 4));
            }
            uint32_t b0[4], b1[4];
            {
                int rowb = wn + lane;
                uint32_t c0 = (uint32_t)((k8    ) ^ (rowb & 7));
                uint32_t c1 = (uint32_t)((k8 + 1) ^ (rowb & 7));
                ldmx4(b0, bbase_s + (uint32_t)rowb * 128 + (c0 << 4));
                ldmx4(b1, bbase_s + (uint32_t)rowb * 128 + (c1 << 4));
            }
            #pragma unroll
            for (int i = 0; i < 4; i++)
                #pragma unroll
                for (int j = 0; j < 4; j++)
                    mma_bf16(acc[i][j], af[i][0], af[i][1], af[i][2], af[i][3],
                             b0[j], b1[j]);
        }
        __syncthreads();
    }

    // ---- epilogue ----
    #pragma unroll
    for (int i = 0; i < 4; i++) {
        int r0 = bm + wm + i * 16 + gid;
        #pragma unroll
        for (int j = 0; j < 4; j++) {
            int c0 = bn + wn + j * 8 + tig * 2;
            float v0 = acc[i][j][0], v1 = acc[i][j][1];
            float v2 = acc[i][j][2], v3 = acc[i][j][3];
            if (residual) {
                const float* rr0 = residual + (size_t)r0 * N + c0;
                const float* rr1 = residual + (size_t)(r0 + 8) * N + c0;
                v0 += rr0[0]; v1 += rr0[1]; v2 += rr1[0]; v3 += rr1[1];
            }
            if constexpr (sizeof(OutT) == 2) {
                __nv_bfloat162 p0 = { __float2bfloat16(v0), __float2bfloat16(v1) };
                __nv_bfloat162 p1 = { __float2bfloat16(v2), __float2bfloat16(v3) };
                *(__nv_bfloat162*)((__nv_bfloat16*)Cz + (size_t)r0 * N + c0)       = p0;
                *(__nv_bfloat162*)((__nv_bfloat16*)Cz + (size_t)(r0 + 8) * N + c0) = p1;
            } else {
                float2 q0 = { v0, v1 }, q1 = { v2, v3 };
                *(float2*)((float*)Cz + (size_t)r0 * N + c0)       = q0;
                *(float2*)((float*)Cz + (size_t)(r0 + 8) * N + c0) = q1;
            }
        }
    }
}

// ---------------- weight transpose + bf16 convert ----------------
__global__ void wtrans_kernel(const float* __restrict__ W,
                              __nv_bfloat16* __restrict__ Wt, int K, int N) {
    __shared__ float tile[32][33];
    int bx = blockIdx.x * 32;   // n
    int by = blockIdx.y * 32;   // k
    int tx = threadIdx.x & 31, ty = threadIdx.x >> 5;
    #pragma unroll
    for (int r = 0; r < 32; r += 8)
        tile[ty + r][tx] = W[(size_t)(by + ty + r) * N + bx + tx];
    __syncthreads();
    #pragma unroll
    for (int r = 0; r < 32; r += 8)
        Wt[(size_t)(bx + ty + r) * K + by + tx] = __float2bfloat16(tile[tx][ty + r]);
}

// padded variant: src N=Nsrc, dst rows Npad (zeros beyond Nsrc)
__global__ void wtrans_pad_kernel(const float* __restrict__ W,
                                  __nv_bfloat16* __restrict__ Wt,
                                  int K, int Nsrc, int Npad) {
    __shared__ float tile[32][33];
    int bx = blockIdx.x * 32;   // n
    int by = blockIdx.y * 32;   // k
    int tx = threadIdx.x & 31, ty = threadIdx.x >> 5;
    #pragma unroll
    for (int r = 0; r < 32; r += 8) {
        int n = bx + tx;
        tile[ty + r][tx] = (n < Nsrc) ? W[(size_t)(by + ty + r) * Nsrc + n] : 0.f;
    }
    __syncthreads();
    #pragma unroll
    for (int r = 0; r < 32; r += 8)
        Wt[(size_t)(bx + ty + r) * K + by + tx] = __float2bfloat16(tile[tx][ty + r]);
}

// ---------------- x_proj reduce: sum 8 partials (float4) ----------------
__global__ void xproj_reduce128() {
    int idx = blockIdx.x * 256 + threadIdx.x;      // float4 index
    float4 s = { 0.f, 0.f, 0.f, 0.f };
    #pragma unroll
    for (int q = 0; q < XKSPLIT; q++) {
        float4 v = *((const float4*)(g_xpf + (size_t)q * TOK * XPAD) + idx);
        s.x += v.x; s.y += v.y; s.z += v.z; s.w += v.w;
    }
    *((float4*)g_xdbl + idx) = s;
}

// ---------------- RMSNorm (bf16 out) ----------------
__global__ void rmsnorm_kernel(const float* __restrict__ x0,
                               const float* __restrict__ w) {
    int t = blockIdx.x;
    const float* xr = x0 + (size_t)t * DMODEL;
    float s = 0.f;
    #pragma unroll
    for (int i = 0; i < DMODEL / 256; i++) {
        float v = xr[threadIdx.x + i * 256];
        s += v * v;
    }
    #pragma unroll
    for (int o = 16; o > 0; o >>= 1) s += __shfl_xor_sync(0xffffffffu, s, o);
    __shared__ float ws[8];
    if ((threadIdx.x & 31) == 0) ws[threadIdx.x >> 5] = s;
    __syncthreads();
    if (threadIdx.x < 8) {
        float v = ws[threadIdx.x];
        #pragma unroll
        for (int o = 4; o > 0; o >>= 1) v += __shfl_xor_sync(0xffu, v, o);
        if (threadIdx.x == 0) ws[0] = v;
    }
    __syncthreads();
    float rs = rsqrtf(ws[0] / (float)DMODEL + EPS);
    __nv_bfloat16* hr = g_hb + (size_t)t * DMODEL;
    #pragma unroll
    for (int i = 0; i < DMODEL / 256; i++) {
        int c = threadIdx.x + i * 256;
        hr[c] = __float2bfloat16(xr[c] * rs * w[c]);
    }
}

// ---------------- causal depthwise conv (K=4) + SiLU, 4 outputs/thread ------
__global__ void conv_silu_kernel(const float* __restrict__ conv_w,
                                 const float* __restrict__ conv_b) {
    int gidx = blockIdx.x * blockDim.x + threadIdx.x;
    int d  = gidx & (DINNER - 1);
    int q  = gidx >> 11;
    int l4 = q & (LSEQ / 4 - 1);
    int b  = q >> 8;
    int l0 = l4 * 4;

    float w0 = conv_w[d * KCONV + 0];
    float w1 = conv_w[d * KCONV + 1];
    float w2 = conv_w[d * KCONV + 2];
    float w3 = conv_w[d * KCONV + 3];
    float cb = conv_b[d];

    const size_t S = 2 * DINNER;
    const __nv_bfloat16* base = g_xresb + (size_t)(b * LSEQ) * S + d;

    float h0 = 0.f, h1 = 0.f, h2 = 0.f;
    if (l0 > 0) {
        h0 = __bfloat162float(base[(size_t)(l0 - 3) * S]);
        h1 = __bfloat162float(base[(size_t)(l0 - 2) * S]);
        h2 = __bfloat162float(base[(size_t)(l0 - 1) * S]);
    }
    float c0 = __bfloat162float(base[(size_t)(l0 + 0) * S]);
    float c1 = __bfloat162float(base[(size_t)(l0 + 1) * S]);
    float c2 = __bfloat162float(base[(size_t)(l0 + 2) * S]);
    float c3 = __bfloat162float(base[(size_t)(l0 + 3) * S]);

    float o0 = fmaf(w0,h0, fmaf(w1,h1, fmaf(w2,h2, fmaf(w3,c0, cb))));
    float o1 = fmaf(w0,h1, fmaf(w1,h2, fmaf(w2,c0, fmaf(w3,c1, cb))));
    float o2 = fmaf(w0,h2, fmaf(w1,c0, fmaf(w2,c1, fmaf(w3,c2, cb))));
    float o3 = fmaf(w0,c0, fmaf(w1,c1, fmaf(w2,c2, fmaf(w3,c3, cb))));

    size_t t0 = (size_t)(b * LSEQ + l0) * DINNER + d;
    g_xcb[t0]              = __float2bfloat16(silu_f(o0));
    g_xcb[t0 + DINNER]     = __float2bfloat16(silu_f(o1));
    g_xcb[t0 + 2 * DINNER] = __float2bfloat16(silu_f(o2));
    g_xcb[t0 + 3 * DINNER] = __float2bfloat16(silu_f(o3));
}

// ---------------- delta: 16 tokens/block, 4 cols/thread, bf16 out ----------
__global__ void delta_kernel(const float* __restrict__ W_dt,
                             const float* __restrict__ b_dt) {
    __shared__ float sd[16][DTRANK];
    int tid = threadIdx.x;
    int t0 = blockIdx.x * 16;
    int cb = blockIdx.y * 1024;
    #pragma unroll
    for (int q = 0; q < 4; q++) {
        int p = tid + 256 * q;
        int tok = p >> 6, k = p & 63;
        sd[tok][k] = g_xdbl[(size_t)(t0 + tok) * XPAD + k];
    }
    __syncthreads();

    float bb[4];
    #pragma unroll
    for (int j = 0; j < 4; j++) bb[j] = b_dt[cb + tid + 256 * j];
    float acc[16][4];
    #pragma unroll
    for (int tok = 0; tok < 16; tok++)
        #pragma unroll
        for (int j = 0; j < 4; j++) acc[tok][j] = bb[j];

    #pragma unroll 4
    for (int k = 0; k < DTRANK; k++) {
        float w[4];
        #pragma unroll
        for (int j = 0; j < 4; j++)
            w[j] = W_dt[(size_t)k * DINNER + cb + tid + 256 * j];
        #pragma unroll
        for (int tok = 0; tok < 16; tok++) {
            float dl = sd[tok][k];
            #pragma unroll
            for (int j = 0; j < 4; j++) acc[tok][j] = fmaf(dl, w[j], acc[tok][j]);
        }
    }
    #pragma unroll
    for (int tok = 0; tok < 16; tok++)
        #pragma unroll
        for (int j = 0; j < 4; j++) {
            float x = acc[tok][j];
            float sp = (x > 20.f) ? x : log1pf(__expf(x));
            g_deltab[(size_t)(t0 + tok) * DINNER + cb + tid + 256 * j] =
                __float2bfloat16(sp);
        }
}

// ---------------- scan pass A (B staged in smem) ----------------
__global__ void scanA_kernel(const float* __restrict__ A) {
    int g = blockIdx.x * blockDim.x + threadIdx.x;
    int tid = threadIdx.x;
    int d  = g & (DINNER - 1);
    int bc = g >> 11;
    int c  = bc & (NCHUNK - 1);
    int b  = bc >> 5;
    int t0 = b * LSEQ + c * CLEN;

    __shared__ float sB[CLEN][DSTATE];
    {
        int l = tid >> 3, n2 = tid & 7;
        float2 v = *(const float2*)(g_xdbl + (size_t)(t0 + l) * XPAD + DTRANK + n2 * 2);
        *(float2*)&sB[l][n2 * 2] = v;
    }
    __syncthreads();

    float a[DSTATE], s[DSTATE], P[DSTATE];
    #pragma unroll
    for (int q = 0; q < 4; q++) {
        float4 v = *(const float4*)(A + d * DSTATE + q * 4);
        a[q*4+0]=v.x; a[q*4+1]=v.y; a[q*4+2]=v.z; a[q*4+3]=v.w;
    }
    #pragma unroll
    for (int n = 0; n < DSTATE; n++) { s[n] = 0.f; P[n] = 1.f; }

    for (int l = 0; l < CLEN; l++) {
        int t = t0 + l;
        float delta = __bfloat162float(g_deltab[(size_t)t * DINNER + d]);
        float xv    = __bfloat162float(g_xcb   [(size_t)t * DINNER + d]);
        float du    = delta * xv;
        #pragma unroll
        for (int n = 0; n < DSTATE; n++) {
            float dA = __expf(delta * a[n]);
            s[n] = fmaf(dA, s[n], du * sB[l][n]);
            P[n] *= dA;
        }
    }
    float* Sp = g_S + (size_t)bc * DN + d * DSTATE;
    float* Pp = g_P + (size_t)bc * DN + d * DSTATE;
    #pragma unroll
    for (int q = 0; q < 4; q++) {
        float4 vs = { s[q*4+0], s[q*4+1], s[q*4+2], s[q*4+3] };
        float4 vp = { P[q*4+0], P[q*4+1], P[q*4+2], P[q*4+3] };
        *(float4*)(Sp + q * 4) = vs;
        *(float4*)(Pp + q * 4) = vp;
    }
}

// ---------------- scan pass B ----------------
__global__ void scanB_kernel() {
    int g = blockIdx.x * blockDim.x + threadIdx.x;
    int idx = g & (DN - 1);
    int b   = g >> 15;
    size_t base = (size_t)b * NCHUNK * DN;
    float s = 0.f;
    for (int c = 0; c < NCHUNK; c++) {
        size_t o = base + (size_t)c * DN + idx;
        g_SI[o] = s;
        s = g_S[o] + g_P[o] * s;
    }
}

// ---------------- scan pass C (B,C staged; bf16 gated output) ----------------
__global__ void scanC_kernel(const float* __restrict__ A,
                             const float* __restrict__ Dp) {
    int g = blockIdx.x * blockDim.x + threadIdx.x;
    int tid = threadIdx.x;
    int d  = g & (DINNER - 1);
    int bc = g >> 11;
    int c  = bc & (NCHUNK - 1);
    int b  = bc >> 5;
    int t0 = b * LSEQ + c * CLEN;

    __shared__ float sB[CLEN][DSTATE];
    __shared__ float sC[CLEN][DSTATE];
    {
        int l = tid >> 3, n2 = tid & 7;
        const float* row = g_xdbl + (size_t)(t0 + l) * XPAD + DTRANK;
        *(float2*)&sB[l][n2 * 2] = *(const float2*)(row + n2 * 2);
        *(float2*)&sC[l][n2 * 2] = *(const float2*)(row + DSTATE + n2 * 2);
    }
    __syncthreads();

    float a[DSTATE], s[DSTATE];
    #pragma unroll
    for (int q = 0; q < 4; q++) {
        float4 v = *(const float4*)(A + d * DSTATE + q * 4);
        a[q*4+0]=v.x; a[q*4+1]=v.y; a[q*4+2]=v.z; a[q*4+3]=v.w;
        float4 vi = *(const float4*)(g_SI + (size_t)bc * DN + d * DSTATE + q * 4);
        s[q*4+0]=vi.x; s[q*4+1]=vi.y; s[q*4+2]=vi.z; s[q*4+3]=vi.w;
    }
    float Dd = Dp[d];

    for (int l = 0; l < CLEN; l++) {
        int t = t0 + l;
        float delta = __bfloat162float(g_deltab[(size_t)t * DINNER + d]);
        float xv    = __bfloat162float(g_xcb   [(size_t)t * DINNER + d]);
        float du    = delta * xv;
        float y = 0.f;
        #pragma unroll
        for (int n = 0; n < DSTATE; n++) {
            float dA = __expf(delta * a[n]);
            s[n] = fmaf(dA, s[n], du * sB[l][n]);
            y = fmaf(s[n], sC[l][n], y);
        }
        float res = __bfloat162float(
            g_xresb[(size_t)t * (2 * DINNER) + DINNER + d]);
        g_yb[(size_t)t * DINNER + d] =
            __float2bfloat16((y + xv * Dd) * silu_f(res));
    }
}

// ---------------- launch ----------------
extern "C" void kernel_launch(void* const* d_in, const int* in_sizes, int n_in,
                              void* d_out, int out_size) {
    const float* x0     = (const float*)d_in[0];
    const float* norm_w = (const float*)d_in[1];
    const float* W_in   = (const float*)d_in[2];
    const float* conv_w = (const float*)d_in[3];
    const float* conv_b = (const float*)d_in[4];
    const float* W_x    = (const float*)d_in[5];
    const float* W_dt   = (const float*)d_in[6];
    const float* b_dt   = (const float*)d_in[7];
    const float* Amat   = (const float*)d_in[8];
    const float* Dvec   = (const float*)d_in[9];
    const float* W_out  = (const float*)d_in[10];
    float* out = (float*)d_out;

    __nv_bfloat16 *p_hb, *p_yb, *p_wint, *p_woutt, *p_wxt, *p_xresb, *p_xcb;
    float *p_xpf;
    cudaGetSymbolAddress((void**)&p_hb,    g_hb);
    cudaGetSymbolAddress((void**)&p_yb,    g_yb);
    cudaGetSymbolAddress((void**)&p_wint,  g_wint);
    cudaGetSymbolAddress((void**)&p_woutt, g_woutt);
    cudaGetSymbolAddress((void**)&p_wxt,   g_wxt);
    cudaGetSymbolAddress((void**)&p_xresb, g_xresb);
    cudaGetSymbolAddress((void**)&p_xcb,   g_xcb);
    cudaGetSymbolAddress((void**)&p_xpf,   g_xpf);

    cudaFuncSetAttribute(gemm_bf16<__nv_bfloat16>,
                         cudaFuncAttributeMaxDynamicSharedMemorySize, GEMM_SMEM);
    cudaFuncSetAttribute(gemm_bf16<float>,
                         cudaFuncAttributeMaxDynamicSharedMemorySize, GEMM_SMEM);

    // weight transposes (bf16)
    wtrans_kernel<<<dim3((2 * DINNER) / 32, DMODEL / 32), 256>>>(
        W_in, p_wint, DMODEL, 2 * DINNER);
    wtrans_kernel<<<dim3(DMODEL / 32, DINNER / 32), 256>>>(
        W_out, p_woutt, DINNER, DMODEL);
    wtrans_pad_kernel<<<dim3(XPAD / 32, DINNER / 32), 256>>>(
        W_x, p_wxt, DINNER, XDBL_N, XPAD);

    // 1) RMSNorm -> bf16
    rmsnorm_kernel<<<TOK, 256>>>(x0, norm_w);

    // 2) in_proj (bf16 mma, bf16 out): [2048,1024] @ [1024,4096]
    gemm_bf16<__nv_bfloat16><<<dim3((2 * DINNER) / 128, TOK / 128), 256, GEMM_SMEM>>>(
        p_hb, p_wint, p_xresb, TOK, 2 * DINNER, DMODEL, DMODEL, DMODEL, nullptr);

    // 3) conv + silu
    conv_silu_kernel<<<(TOK / 4 * DINNER) / 256, 256>>>(conv_w, conv_b);

    // 4) x_proj: split-K bf16 mma -> partials -> reduce
    gemm_bf16<float><<<dim3(1, TOK / 128, XKSPLIT), 256, GEMM_SMEM>>>(
        p_xcb, p_wxt, p_xpf, TOK, XPAD, DINNER, DINNER, DINNER / XKSPLIT, nullptr);
    xproj_reduce128<<<TOK * XPAD / 4 / 256, 256>>>();

    // 5) delta
    delta_kernel<<<dim3(TOK / 16, 2), 256>>>(W_dt, b_dt);

    // 6) chunked selective scan
    scanA_kernel<<<(BATCH * NCHUNK * DINNER) / 256, 256>>>(Amat);
    scanB_kernel<<<(BATCH * DN) / 256, 256>>>();
    scanC_kernel<<<(BATCH * NCHUNK * DINNER) / 256, 256>>>(Amat, Dvec);

    // 7) out_proj (bf16 mma, fp32 out) + residual: [2048,2048] @ [2048,1024]
    gemm_bf16<float><<<dim3(DMODEL / 128, TOK / 128), 256, GEMM_SMEM>>>(
        p_yb, p_woutt, out, TOK, DMODEL, DINNER, DINNER, DINNER, x0);
}

// round 8
// speedup vs baseline: 8.9290x; 1.0163x over previous
#include <cuda_runtime.h>
#include <cuda_bf16.h>
#include <cuda_fp8.h>
#include <math.h>
#include <stdint.h>

// ---------------- problem constants ----------------
#define BATCH   2
#define LSEQ    1024
#define DMODEL  1024
#define DINNER  2048
#define DSTATE  16
#define DTRANK  64
#define KCONV   4
#define TOK     (BATCH*LSEQ)        // 2048 tokens
#define XDBL_N  96
#define XPAD    128                 // padded xdbl stride
#define EPS     1e-5f

#define NCHUNK  32
#define CLEN    (LSEQ/NCHUNK)       // 32
#define DN      (DINNER*DSTATE)     // 32768
#define XKSPLIT 8                   // x_proj K splits (MMA)

// ---------------- scratch ----------------
__device__ __align__(16) uint8_t        g_h8    [TOK * DMODEL];       // rmsnorm out (e4m3)
__device__ __align__(16) uint8_t        g_y8    [TOK * DINNER];       // scan out (e4m3)
__device__ __align__(16) uint8_t        g_wint8 [2*DINNER * DMODEL];  // W_in^T  e4m3
__device__ __align__(16) uint8_t        g_woutt8[DMODEL * DINNER];    // W_out^T e4m3
__device__ __align__(16) __nv_bfloat16 g_wxt   [XPAD * DINNER];      // W_x^T padded bf16
__device__ __align__(16) __nv_bfloat16 g_xresb [TOK * 2 * DINNER];   // in_proj out
__device__ __align__(16) __nv_bfloat16 g_xcb   [TOK * DINNER];       // conv+silu out
__device__ __align__(16) __nv_bfloat16 g_deltab[TOK * DINNER];       // softplus(dt)
__device__ __align__(16) float g_xdbl [TOK * XPAD];                  // x_proj out (padded)
__device__ __align__(16) float g_xpf  [XKSPLIT * TOK * XPAD];        // x_proj partials
__device__ __align__(16) float g_S    [BATCH * NCHUNK * DN];
__device__ __align__(16) float g_P    [BATCH * NCHUNK * DN];
__device__ __align__(16) float g_SI   [BATCH * NCHUNK * DN];

// ---------------- helpers ----------------
__device__ __forceinline__ float silu_f(float x) {
    return x / (1.f + __expf(-x));
}
__device__ __forceinline__ void cp16(uint32_t smem, const void* g) {
    asm volatile("cp.async.cg.shared.global [%0], [%1], 16;\n" :: "r"(smem), "l"(g));
}
__device__ __forceinline__ uint8_t f2e4m3(float f) {
    return (uint8_t)__nv_cvt_float_to_fp8(f, __NV_SATFINITE, __NV_E4M3);
}
__device__ __forceinline__ void mma_bf16(float c[4],
    uint32_t a0, uint32_t a1, uint32_t a2, uint32_t a3,
    uint32_t b0, uint32_t b1) {
    asm volatile(
        "mma.sync.aligned.m16n8k16.row.col.f32.bf16.bf16.f32 "
        "{%0,%1,%2,%3}, {%4,%5,%6,%7}, {%8,%9}, {%0,%1,%2,%3};"
        : "+f"(c[0]), "+f"(c[1]), "+f"(c[2]), "+f"(c[3])
        : "r"(a0), "r"(a1), "r"(a2), "r"(a3), "r"(b0), "r"(b1));
}
__device__ __forceinline__ void mma_e4m3(float c[4],
    uint32_t a0, uint32_t a1, uint32_t a2, uint32_t a3,
    uint32_t b0, uint32_t b1) {
    asm volatile(
        "mma.sync.aligned.m16n8k32.row.col.f32.e4m3.e4m3.f32 "
        "{%0,%1,%2,%3}, {%4,%5,%6,%7}, {%8,%9}, {%0,%1,%2,%3};"
        : "+f"(c[0]), "+f"(c[1]), "+f"(c[2]), "+f"(c[3])
        : "r"(a0), "r"(a1), "r"(a2), "r"(a3), "r"(b0), "r"(b1));
}
__device__ __forceinline__ void ldmx4(uint32_t r[4], uint32_t addr) {
    asm volatile(
        "ldmatrix.sync.aligned.m8n8.x4.shared.b16 {%0,%1,%2,%3}, [%4];"
        : "=r"(r[0]), "=r"(r[1]), "=r"(r[2]), "=r"(r[3]) : "r"(addr));
}

#define GSTG   16384u
#define NSTAGE 3
#define GEMM_SMEM (2 * NSTAGE * GSTG)     // 96 KB

// ---------------- bf16 MMA GEMM (x_proj path), split-K capable ----------
template <typename OutT>
__global__ void __launch_bounds__(256)
gemm_bf16(const __nv_bfloat16* __restrict__ A, const __nv_bfloat16* __restrict__ Bt,
          OutT* __restrict__ C, int M, int N, int lda, int ldb, int Kslice,
          const float* __restrict__ residual) {
    extern __shared__ char smem[];
    uint32_t smem_base;
    asm("{ .reg .u64 t; cvta.to.shared.u64 t, %1; cvt.u32.u64 %0, t; }"
        : "=r"(smem_base) : "l"(smem));

    int tid  = threadIdx.x;
    int lane = tid & 31, wid = tid >> 5;
    int bm = blockIdx.y * 128, bn = blockIdx.x * 128;
    int wm = (wid >> 2) * 64, wn = (wid & 3) * 32;
    int gid = lane >> 2, tig = lane & 3;
    int koff = blockIdx.z * Kslice;

    float acc[4][4][4];
    #pragma unroll
    for (int i = 0; i < 4; i++)
        #pragma unroll
        for (int j = 0; j < 4; j++)
            #pragma unroll
            for (int q = 0; q < 4; q++) acc[i][j][q] = 0.f;

    const __nv_bfloat16* abase = A + (size_t)bm * lda + koff;
    const __nv_bfloat16* bbase = Bt + (size_t)bn * ldb + koff;
    OutT* Cz = C + (size_t)blockIdx.z * M * N;

    int lrow = tid >> 3;
    int lch  = tid & 7;

    auto load_stage = [&](int s, int kt) {
        uint32_t adst = smem_base + (uint32_t)s * GSTG;
        uint32_t bdst = smem_base + NSTAGE * GSTG + (uint32_t)s * GSTG;
        const __nv_bfloat16* asrc = abase + (size_t)kt * 64;
        const __nv_bfloat16* bsrc = bbase + (size_t)kt * 64;
        #pragma unroll
        for (int u = 0; u < 4; u++) {
            int row = lrow + u * 32;
            uint32_t d = (uint32_t)row * 128 + ((uint32_t)(lch ^ (row & 7)) << 4);
            cp16(adst + d, asrc + (size_t)row * lda + lch * 8);
            cp16(bdst + d, bsrc + (size_t)row * ldb + lch * 8);
        }
        asm volatile("cp.async.commit_group;\n");
    };

    int nt = Kslice / 64;
    load_stage(0, 0);
    load_stage(1, 1);

    for (int t = 0; t < nt; t++) {
        int s = t % NSTAGE;
        if (t + 1 < nt) asm volatile("cp.async.wait_group 1;\n" ::: "memory");
        else            asm volatile("cp.async.wait_group 0;\n" ::: "memory");
        __syncthreads();
        if (t + 2 < nt) load_stage((t + 2) % NSTAGE, t + 2);

        uint32_t abase_s = smem_base + (uint32_t)s * GSTG;
        uint32_t bbase_s = smem_base + NSTAGE * GSTG + (uint32_t)s * GSTG;

        #pragma unroll
        for (int ks = 0; ks < 4; ks++) {
            int k8 = ks * 2;
            uint32_t af[4][4];
            #pragma unroll
            for (int i = 0; i < 4; i++) {
                int row = wm + i * 16 + (lane & 15);
                uint32_t ch = (uint32_t)((k8 + (lane >> 4)) ^ (row & 7));
                ldmx4(af[i], abase_s + (uint32_t)row * 128 + (ch << 4));
            }
            uint32_t b0[4], b1[4];
            {
                int rowb = wn + lane;
                uint32_t c0 = (uint32_t)((k8    ) ^ (rowb & 7));
                uint32_t c1 = (uint32_t)((k8 + 1) ^ (rowb & 7));
                ldmx4(b0, bbase_s + (uint32_t)rowb * 128 + (c0 << 4));
                ldmx4(b1, bbase_s + (uint32_t)rowb * 128 + (c1 << 4));
            }
            #pragma unroll
            for (int i = 0; i < 4; i++)
                #pragma unroll
                for (int j = 0; j < 4; j++)
                    mma_bf16(acc[i][j], af[i][0], af[i][1], af[i][2], af[i][3],
                             b0[j], b1[j]);
        }
        __syncthreads();
    }

    #pragma unroll
    for (int i = 0; i < 4; i++) {
        int r0 = bm + wm + i * 16 + gid;
        #pragma unroll
        for (int j = 0; j < 4; j++) {
            int c0 = bn + wn + j * 8 + tig * 2;
            float v0 = acc[i][j][0], v1 = acc[i][j][1];
            float v2 = acc[i][j][2], v3 = acc[i][j][3];
            if (residual) {
                const float* rr0 = residual + (size_t)r0 * N + c0;
                const float* rr1 = residual + (size_t)(r0 + 8) * N + c0;
                v0 += rr0[0]; v1 += rr0[1]; v2 += rr1[0]; v3 += rr1[1];
            }
            if constexpr (sizeof(OutT) == 2) {
                __nv_bfloat162 p0 = { __float2bfloat16(v0), __float2bfloat16(v1) };
                __nv_bfloat162 p1 = { __float2bfloat16(v2), __float2bfloat16(v3) };
                *(__nv_bfloat162*)((__nv_bfloat16*)Cz + (size_t)r0 * N + c0)       = p0;
                *(__nv_bfloat162*)((__nv_bfloat16*)Cz + (size_t)(r0 + 8) * N + c0) = p1;
            } else {
                float2 q0 = { v0, v1 }, q1 = { v2, v3 };
                *(float2*)((float*)Cz + (size_t)r0 * N + c0)       = q0;
                *(float2*)((float*)Cz + (size_t)(r0 + 8) * N + c0) = q1;
            }
        }
    }
}

// ---------------- FP8 e4m3 MMA GEMM (in_proj / out_proj) --------------------
// Same tile machinery; 128 fp8 per 128B row, BK=128, mma m16n8k32.
// fp8 k32 fragments are byte-identical to bf16 k16 fragments (b16 = fp8 pair),
// so the swizzled ldmatrix.b16 indexing carries over unchanged.
template <typename OutT>
__global__ void __launch_bounds__(256)
gemm_fp8(const uint8_t* __restrict__ A, const uint8_t* __restrict__ Bt,
         OutT* __restrict__ C, int M, int N, int lda, int ldb, int Kslice,
         const float* __restrict__ residual) {
    extern __shared__ char smem[];
    uint32_t smem_base;
    asm("{ .reg .u64 t; cvta.to.shared.u64 t, %1; cvt.u32.u64 %0, t; }"
        : "=r"(smem_base) : "l"(smem));

    int tid  = threadIdx.x;
    int lane = tid & 31, wid = tid >> 5;
    int bm = blockIdx.y * 128, bn = blockIdx.x * 128;
    int wm = (wid >> 2) * 64, wn = (wid & 3) * 32;
    int gid = lane >> 2, tig = lane & 3;

    float acc[4][4][4];
    #pragma unroll
    for (int i = 0; i < 4; i++)
        #pragma unroll
        for (int j = 0; j < 4; j++)
            #pragma unroll
            for (int q = 0; q < 4; q++) acc[i][j][q] = 0.f;

    const uint8_t* abase = A + (size_t)bm * lda;
    const uint8_t* bbase = Bt + (size_t)bn * ldb;

    int lrow = tid >> 3;
    int lch  = tid & 7;

    auto load_stage = [&](int s, int kt) {
        uint32_t adst = smem_base + (uint32_t)s * GSTG;
        uint32_t bdst = smem_base + NSTAGE * GSTG + (uint32_t)s * GSTG;
        const uint8_t* asrc = abase + (size_t)kt * 128;
        const uint8_t* bsrc = bbase + (size_t)kt * 128;
        #pragma unroll
        for (int u = 0; u < 4; u++) {
            int row = lrow + u * 32;
            uint32_t d = (uint32_t)row * 128 + ((uint32_t)(lch ^ (row & 7)) << 4);
            cp16(adst + d, asrc + (size_t)row * lda + lch * 16);
            cp16(bdst + d, bsrc + (size_t)row * ldb + lch * 16);
        }
        asm volatile("cp.async.commit_group;\n");
    };

    int nt = Kslice / 128;          // >= 2 for all calls here
    load_stage(0, 0);
    load_stage(1, 1);

    for (int t = 0; t < nt; t++) {
        int s = t % NSTAGE;
        if (t + 1 < nt) asm volatile("cp.async.wait_group 1;\n" ::: "memory");
        else            asm volatile("cp.async.wait_group 0;\n" ::: "memory");
        __syncthreads();
        if (t + 2 < nt) load_stage((t + 2) % NSTAGE, t + 2);

        uint32_t abase_s = smem_base + (uint32_t)s * GSTG;
        uint32_t bbase_s = smem_base + NSTAGE * GSTG + (uint32_t)s * GSTG;

        #pragma unroll
        for (int ks = 0; ks < 4; ks++) {      // 4 x k32 = 128 fp8 per stage
            int k8 = ks * 2;
            uint32_t af[4][4];
            #pragma unroll
            for (int i = 0; i < 4; i++) {
                int row = wm + i * 16 + (lane & 15);
                uint32_t ch = (uint32_t)((k8 + (lane >> 4)) ^ (row & 7));
                ldmx4(af[i], abase_s + (uint32_t)row * 128 + (ch << 4));
            }
            uint32_t b0[4], b1[4];
            {
                int rowb = wn + lane;
                uint32_t c0 = (uint32_t)((k8    ) ^ (rowb & 7));
                uint32_t c1 = (uint32_t)((k8 + 1) ^ (rowb & 7));
                ldmx4(b0, bbase_s + (uint32_t)rowb * 128 + (c0 << 4));
                ldmx4(b1, bbase_s + (uint32_t)rowb * 128 + (c1 << 4));
            }
            #pragma unroll
            for (int i = 0; i < 4; i++)
                #pragma unroll
                for (int j = 0; j < 4; j++)
                    mma_e4m3(acc[i][j], af[i][0], af[i][1], af[i][2], af[i][3],
                             b0[j], b1[j]);
        }
        __syncthreads();
    }

    #pragma unroll
    for (int i = 0; i < 4; i++) {
        int r0 = bm + wm + i * 16 + gid;
        #pragma unroll
        for (int j = 0; j < 4; j++) {
            int c0 = bn + wn + j * 8 + tig * 2;
            float v0 = acc[i][j][0], v1 = acc[i][j][1];
            float v2 = acc[i][j][2], v3 = acc[i][j][3];
            if (residual) {
                const float* rr0 = residual + (size_t)r0 * N + c0;
                const float* rr1 = residual + (size_t)(r0 + 8) * N + c0;
                v0 += rr0[0]; v1 += rr0[1]; v2 += rr1[0]; v3 += rr1[1];
            }
            if constexpr (sizeof(OutT) == 2) {
                __nv_bfloat162 p0 = { __float2bfloat16(v0), __float2bfloat16(v1) };
                __nv_bfloat162 p1 = { __float2bfloat16(v2), __float2bfloat16(v3) };
                *(__nv_bfloat162*)((__nv_bfloat16*)C + (size_t)r0 * N + c0)       = p0;
                *(__nv_bfloat162*)((__nv_bfloat16*)C + (size_t)(r0 + 8) * N + c0) = p1;
            } else {
                float2 q0 = { v0, v1 }, q1 = { v2, v3 };
                *(float2*)((float*)C + (size_t)r0 * N + c0)       = q0;
                *(float2*)((float*)C + (size_t)(r0 + 8) * N + c0) = q1;
            }
        }
    }
}

// ---------------- weight transpose -> fp8 e4m3 ----------------
__global__ void wtrans8_kernel(const float* __restrict__ W,
                               uint8_t* __restrict__ Wt, int K, int N) {
    __shared__ float tile[32][33];
    int bx = blockIdx.x * 32;   // n
    int by = blockIdx.y * 32;   // k
    int tx = threadIdx.x & 31, ty = threadIdx.x >> 5;
    #pragma unroll
    for (int r = 0; r < 32; r += 8)
        tile[ty + r][tx] = W[(size_t)(by + ty + r) * N + bx + tx];
    __syncthreads();
    #pragma unroll
    for (int r = 0; r < 32; r += 8)
        Wt[(size_t)(bx + ty + r) * K + by + tx] = f2e4m3(tile[tx][ty + r]);
}

// padded bf16 variant (W_x)
__global__ void wtrans_pad_kernel(const float* __restrict__ W,
                                  __nv_bfloat16* __restrict__ Wt,
                                  int K, int Nsrc, int Npad) {
    __shared__ float tile[32][33];
    int bx = blockIdx.x * 32;
    int by = blockIdx.y * 32;
    int tx = threadIdx.x & 31, ty = threadIdx.x >> 5;
    #pragma unroll
    for (int r = 0; r < 32; r += 8) {
        int n = bx + tx;
        tile[ty + r][tx] = (n < Nsrc) ? W[(size_t)(by + ty + r) * Nsrc + n] : 0.f;
    }
    __syncthreads();
    #pragma unroll
    for (int r = 0; r < 32; r += 8)
        Wt[(size_t)(bx + ty + r) * K + by + tx] = __float2bfloat16(tile[tx][ty + r]);
}

// ---------------- x_proj reduce ----------------
__global__ void xproj_reduce128() {
    int idx = blockIdx.x * 256 + threadIdx.x;
    float4 s = { 0.f, 0.f, 0.f, 0.f };
    #pragma unroll
    for (int q = 0; q < XKSPLIT; q++) {
        float4 v = *((const float4*)(g_xpf + (size_t)q * TOK * XPAD) + idx);
        s.x += v.x; s.y += v.y; s.z += v.z; s.w += v.w;
    }
    *((float4*)g_xdbl + idx) = s;
}

// ---------------- RMSNorm (fp8 out) ----------------
__global__ void rmsnorm_kernel(const float* __restrict__ x0,
                               const float* __restrict__ w) {
    int t = blockIdx.x;
    const float* xr = x0 + (size_t)t * DMODEL;
    float s = 0.f;
    #pragma unroll
    for (int i = 0; i < DMODEL / 256; i++) {
        float v = xr[threadIdx.x + i * 256];
        s += v * v;
    }
    #pragma unroll
    for (int o = 16; o > 0; o >>= 1) s += __shfl_xor_sync(0xffffffffu, s, o);
    __shared__ float ws[8];
    if ((threadIdx.x & 31) == 0) ws[threadIdx.x >> 5] = s;
    __syncthreads();
    if (threadIdx.x < 8) {
        float v = ws[threadIdx.x];
        #pragma unroll
        for (int o = 4; o > 0; o >>= 1) v += __shfl_xor_sync(0xffu, v, o);
        if (threadIdx.x == 0) ws[0] = v;
    }
    __syncthreads();
    float rs = rsqrtf(ws[0] / (float)DMODEL + EPS);
    uint8_t* hr = g_h8 + (size_t)t * DMODEL;
    #pragma unroll
    for (int i = 0; i < DMODEL / 512; i++) {
        int c = 2 * threadIdx.x + i * 512;
        uint16_t pk = (uint16_t)f2e4m3(xr[c] * rs * w[c])
                    | ((uint16_t)f2e4m3(xr[c + 1] * rs * w[c + 1]) << 8);
        *(uint16_t*)(hr + c) = pk;
    }
}

// ---------------- causal depthwise conv (K=4) + SiLU ----------------
__global__ void conv_silu_kernel(const float* __restrict__ conv_w,
                                 const float* __restrict__ conv_b) {
    int gidx = blockIdx.x * blockDim.x + threadIdx.x;
    int d  = gidx & (DINNER - 1);
    int q  = gidx >> 11;
    int l4 = q & (LSEQ / 4 - 1);
    int b  = q >> 8;
    int l0 = l4 * 4;

    float w0 = conv_w[d * KCONV + 0];
    float w1 = conv_w[d * KCONV + 1];
    float w2 = conv_w[d * KCONV + 2];
    float w3 = conv_w[d * KCONV + 3];
    float cb = conv_b[d];

    const size_t S = 2 * DINNER;
    const __nv_bfloat16* base = g_xresb + (size_t)(b * LSEQ) * S + d;

    float h0 = 0.f, h1 = 0.f, h2 = 0.f;
    if (l0 > 0) {
        h0 = __bfloat162float(base[(size_t)(l0 - 3) * S]);
        h1 = __bfloat162float(base[(size_t)(l0 - 2) * S]);
        h2 = __bfloat162float(base[(size_t)(l0 - 1) * S]);
    }
    float c0 = __bfloat162float(base[(size_t)(l0 + 0) * S]);
    float c1 = __bfloat162float(base[(size_t)(l0 + 1) * S]);
    float c2 = __bfloat162float(base[(size_t)(l0 + 2) * S]);
    float c3 = __bfloat162float(base[(size_t)(l0 + 3) * S]);

    float o0 = fmaf(w0,h0, fmaf(w1,h1, fmaf(w2,h2, fmaf(w3,c0, cb))));
    float o1 = fmaf(w0,h1, fmaf(w1,h2, fmaf(w2,c0, fmaf(w3,c1, cb))));
    float o2 = fmaf(w0,h2, fmaf(w1,c0, fmaf(w2,c1, fmaf(w3,c2, cb))));
    float o3 = fmaf(w0,c0, fmaf(w1,c1, fmaf(w2,c2, fmaf(w3,c3, cb))));

    size_t t0 = (size_t)(b * LSEQ + l0) * DINNER + d;
    g_xcb[t0]              = __float2bfloat16(silu_f(o0));
    g_xcb[t0 + DINNER]     = __float2bfloat16(silu_f(o1));
    g_xcb[t0 + 2 * DINNER] = __float2bfloat16(silu_f(o2));
    g_xcb[t0 + 3 * DINNER] = __float2bfloat16(silu_f(o3));
}

// ---------------- delta: 16 tokens/block, 4 cols/thread, bf16 out ----------
__global__ void delta_kernel(const float* __restrict__ W_dt,
                             const float* __restrict__ b_dt) {
    __shared__ float sd[16][DTRANK];
    int tid = threadIdx.x;
    int t0 = blockIdx.x * 16;
    int cb = blockIdx.y * 1024;
    #pragma unroll
    for (int q = 0; q < 4; q++) {
        int p = tid + 256 * q;
        int tok = p >> 6, k = p & 63;
        sd[tok][k] = g_xdbl[(size_t)(t0 + tok) * XPAD + k];
    }
    __syncthreads();

    float bb[4];
    #pragma unroll
    for (int j = 0; j < 4; j++) bb[j] = b_dt[cb + tid + 256 * j];
    float acc[16][4];
    #pragma unroll
    for (int tok = 0; tok < 16; tok++)
        #pragma unroll
        for (int j = 0; j < 4; j++) acc[tok][j] = bb[j];

    #pragma unroll 4
    for (int k = 0; k < DTRANK; k++) {
        float w[4];
        #pragma unroll
        for (int j = 0; j < 4; j++)
            w[j] = W_dt[(size_t)k * DINNER + cb + tid + 256 * j];
        #pragma unroll
        for (int tok = 0; tok < 16; tok++) {
            float dl = sd[tok][k];
            #pragma unroll
            for (int j = 0; j < 4; j++) acc[tok][j] = fmaf(dl, w[j], acc[tok][j]);
        }
    }
    #pragma unroll
    for (int tok = 0; tok < 16; tok++)
        #pragma unroll
        for (int j = 0; j < 4; j++) {
            float x = acc[tok][j];
            float sp = (x > 20.f) ? x : log1pf(__expf(x));
            g_deltab[(size_t)(t0 + tok) * DINNER + cb + tid + 256 * j] =
                __float2bfloat16(sp);
        }
}

// ---------------- scan pass A (B staged in smem) ----------------
__global__ void scanA_kernel(const float* __restrict__ A) {
    int g = blockIdx.x * blockDim.x + threadIdx.x;
    int tid = threadIdx.x;
    int d  = g & (DINNER - 1);
    int bc = g >> 11;
    int c  = bc & (NCHUNK - 1);
    int b  = bc >> 5;
    int t0 = b * LSEQ + c * CLEN;

    __shared__ float sB[CLEN][DSTATE];
    {
        int l = tid >> 3, n2 = tid & 7;
        float2 v = *(const float2*)(g_xdbl + (size_t)(t0 + l) * XPAD + DTRANK + n2 * 2);
        *(float2*)&sB[l][n2 * 2] = v;
    }
    __syncthreads();

    float a[DSTATE], s[DSTATE], P[DSTATE];
    #pragma unroll
    for (int q = 0; q < 4; q++) {
        float4 v = *(const float4*)(A + d * DSTATE + q * 4);
        a[q*4+0]=v.x; a[q*4+1]=v.y; a[q*4+2]=v.z; a[q*4+3]=v.w;
    }
    #pragma unroll
    for (int n = 0; n < DSTATE; n++) { s[n] = 0.f; P[n] = 1.f; }

    for (int l = 0; l < CLEN; l++) {
        int t = t0 + l;
        float delta = __bfloat162float(g_deltab[(size_t)t * DINNER + d]);
        float xv    = __bfloat162float(g_xcb   [(size_t)t * DINNER + d]);
        float du    = delta * xv;
        #pragma unroll
        for (int n = 0; n < DSTATE; n++) {
            float dA = __expf(delta * a[n]);
            s[n] = fmaf(dA, s[n], du * sB[l][n]);
            P[n] *= dA;
        }
    }
    float* Sp = g_S + (size_t)bc * DN + d * DSTATE;
    float* Pp = g_P + (size_t)bc * DN + d * DSTATE;
    #pragma unroll
    for (int q = 0; q < 4; q++) {
        float4 vs = { s[q*4+0], s[q*4+1], s[q*4+2], s[q*4+3] };
        float4 vp = { P[q*4+0], P[q*4+1], P[q*4+2], P[q*4+3] };
        *(float4*)(Sp + q * 4) = vs;
        *(float4*)(Pp + q * 4) = vp;
    }
}

// ---------------- scan pass B ----------------
__global__ void scanB_kernel() {
    int g = blockIdx.x * blockDim.x + threadIdx.x;
    int idx = g & (DN - 1);
    int b   = g >> 15;
    size_t base = (size_t)b * NCHUNK * DN;
    float s = 0.f;
    for (int c = 0; c < NCHUNK; c++) {
        size_t o = base + (size_t)c * DN + idx;
        g_SI[o] = s;
        s = g_S[o] + g_P[o] * s;
    }
}

// ---------------- scan pass C (B,C staged; fp8 gated output) ----------------
__global__ void scanC_kernel(const float* __restrict__ A,
                             const float* __restrict__ Dp) {
    int g = blockIdx.x * blockDim.x + threadIdx.x;
    int tid = threadIdx.x;
    int d  = g & (DINNER - 1);
    int bc = g >> 11;
    int c  = bc & (NCHUNK - 1);
    int b  = bc >> 5;
    int t0 = b * LSEQ + c * CLEN;

    __shared__ float sB[CLEN][DSTATE];
    __shared__ float sC[CLEN][DSTATE];
    {
        int l = tid >> 3, n2 = tid & 7;
        const float* row = g_xdbl + (size_t)(t0 + l) * XPAD + DTRANK;
        *(float2*)&sB[l][n2 * 2] = *(const float2*)(row + n2 * 2);
        *(float2*)&sC[l][n2 * 2] = *(const float2*)(row + DSTATE + n2 * 2);
    }
    __syncthreads();

    float a[DSTATE], s[DSTATE];
    #pragma unroll
    for (int q = 0; q < 4; q++) {
        float4 v = *(const float4*)(A + d * DSTATE + q * 4);
        a[q*4+0]=v.x; a[q*4+1]=v.y; a[q*4+2]=v.z; a[q*4+3]=v.w;
        float4 vi = *(const float4*)(g_SI + (size_t)bc * DN + d * DSTATE + q * 4);
        s[q*4+0]=vi.x; s[q*4+1]=vi.y; s[q*4+2]=vi.z; s[q*4+3]=vi.w;
    }
    float Dd = Dp[d];

    for (int l = 0; l < CLEN; l++) {
        int t = t0 + l;
        float delta = __bfloat162float(g_deltab[(size_t)t * DINNER + d]);
        float xv    = __bfloat162float(g_xcb   [(size_t)t * DINNER + d]);
        float du    = delta * xv;
        float y = 0.f;
        #pragma unroll
        for (int n = 0; n < DSTATE; n++) {
            float dA = __expf(delta * a[n]);
            s[n] = fmaf(dA, s[n], du * sB[l][n]);
            y = fmaf(s[n], sC[l][n], y);
        }
        float res = __bfloat162float(
            g_xresb[(size_t)t * (2 * DINNER) + DINNER + d]);
        g_y8[(size_t)t * DINNER + d] =
            f2e4m3((y + xv * Dd) * silu_f(res));
    }
}

// ---------------- launch ----------------
extern "C" void kernel_launch(void* const* d_in, const int* in_sizes, int n_in,
                              void* d_out, int out_size) {
    const float* x0     = (const float*)d_in[0];
    const float* norm_w = (const float*)d_in[1];
    const float* W_in   = (const float*)d_in[2];
    const float* conv_w = (const float*)d_in[3];
    const float* conv_b = (const float*)d_in[4];
    const float* W_x    = (const float*)d_in[5];
    const float* W_dt   = (const float*)d_in[6];
    const float* b_dt   = (const float*)d_in[7];
    const float* Amat   = (const float*)d_in[8];
    const float* Dvec   = (const float*)d_in[9];
    const float* W_out  = (const float*)d_in[10];
    float* out = (float*)d_out;

    uint8_t *p_h8, *p_y8, *p_wint8, *p_woutt8;
    __nv_bfloat16 *p_wxt, *p_xresb, *p_xcb;
    float *p_xpf;
    cudaGetSymbolAddress((void**)&p_h8,     g_h8);
    cudaGetSymbolAddress((void**)&p_y8,     g_y8);
    cudaGetSymbolAddress((void**)&p_wint8,  g_wint8);
    cudaGetSymbolAddress((void**)&p_woutt8, g_woutt8);
    cudaGetSymbolAddress((void**)&p_wxt,    g_wxt);
    cudaGetSymbolAddress((void**)&p_xresb,  g_xresb);
    cudaGetSymbolAddress((void**)&p_xcb,    g_xcb);
    cudaGetSymbolAddress((void**)&p_xpf,    g_xpf);

    cudaFuncSetAttribute(gemm_bf16<float>,
                         cudaFuncAttributeMaxDynamicSharedMemorySize, GEMM_SMEM);
    cudaFuncSetAttribute(gemm_fp8<__nv_bfloat16>,
                         cudaFuncAttributeMaxDynamicSharedMemorySize, GEMM_SMEM);
    cudaFuncSetAttribute(gemm_fp8<float>,
                         cudaFuncAttributeMaxDynamicSharedMemorySize, GEMM_SMEM);

    // weight transposes
    wtrans8_kernel<<<dim3((2 * DINNER) / 32, DMODEL / 32), 256>>>(
        W_in, p_wint8, DMODEL, 2 * DINNER);
    wtrans8_kernel<<<dim3(DMODEL / 32, DINNER / 32), 256>>>(
        W_out, p_woutt8, DINNER, DMODEL);
    wtrans_pad_kernel<<<dim3(XPAD / 32, DINNER / 32), 256>>>(
        W_x, p_wxt, DINNER, XDBL_N, XPAD);

    // 1) RMSNorm -> fp8
    rmsnorm_kernel<<<TOK, 256>>>(x0, norm_w);

    // 2) in_proj (fp8 mma, bf16 out): [2048,1024] @ [1024,4096]
    gemm_fp8<__nv_bfloat16><<<dim3((2 * DINNER) / 128, TOK / 128), 256, GEMM_SMEM>>>(
        p_h8, p_wint8, p_xresb, TOK, 2 * DINNER, DMODEL, DMODEL, DMODEL, nullptr);

    // 3) conv + silu
    conv_silu_kernel<<<(TOK / 4 * DINNER) / 256, 256>>>(conv_w, conv_b);

    // 4) x_proj: split-K bf16 mma -> partials -> reduce
    gemm_bf16<float><<<dim3(1, TOK / 128, XKSPLIT), 256, GEMM_SMEM>>>(
        p_xcb, p_wxt, p_xpf, TOK, XPAD, DINNER, DINNER, DINNER / XKSPLIT, nullptr);
    xproj_reduce128<<<TOK * XPAD / 4 / 256, 256>>>();

    // 5) delta
    delta_kernel<<<dim3(TOK / 16, 2), 256>>>(W_dt, b_dt);

    // 6) chunked selective scan
    scanA_kernel<<<(BATCH * NCHUNK * DINNER) / 256, 256>>>(Amat);
    scanB_kernel<<<(BATCH * DN) / 256, 256>>>();
    scanC_kernel<<<(BATCH * NCHUNK * DINNER) / 256, 256>>>(Amat, Dvec);

    // 7) out_proj (fp8 mma, fp32 out) + residual: [2048,2048] @ [2048,1024]
    gemm_fp8<float><<<dim3(DMODEL / 128, TOK / 128), 256, GEMM_SMEM>>>(
        p_y8, p_woutt8, out, TOK, DMODEL, DINNER, DINNER, DINNER, x0);
}